// round 3
// baseline (speedup 1.0000x reference)
#include <cuda_runtime.h>
#include <cstdint>

#define N_MAX 100000
#define E_MAX 400000

// ---------------- scratch (__device__ globals; no allocation allowed) ----
__device__ __align__(16) float g_agg1[(size_t)N_MAX * 128];   // 51.2 MB
__device__ __align__(16) float g_h   [(size_t)N_MAX * 256];   // 102.4 MB
__device__ __align__(16) float g_t   [(size_t)N_MAX * 64];    // 25.6 MB
__device__ __align__(16) float g_agg2[(size_t)N_MAX * 64];    // 25.6 MB
__device__ int   g_src   [E_MAX];
__device__ int   g_dst   [E_MAX];
__device__ int   g_cnt   [N_MAX];
__device__ int   g_rowptr[N_MAX + 1];
__device__ int   g_cursor[N_MAX];
__device__ int   g_esrc  [E_MAX];
__device__ int   g_bsums [256];
__device__ int   g_boffs [256];
__device__ int   g_is32;          // 1 if edge_index staged as int32

// ---------------- edge dtype probe + normalize ---------------------------
__global__ void reset_kernel(int Nn) {
    int i = blockIdx.x * blockDim.x + threadIdx.x;
    if (i < Nn) g_cnt[i] = 0;
    if (i == 0) g_is32 = 0;
}

// Read first E slots as int64. Safe under both layouts (covers <= the buffer).
// int32 staging makes values >= 2^32 virtually everywhere -> flag.
__global__ void probe_kernel(const void* __restrict__ ei, int E, int Nn) {
    int e = blockIdx.x * blockDim.x + threadIdx.x;
    if (e >= E) return;
    long long v = ((const long long*)ei)[e];
    if (v < 0 || v >= (long long)Nn) g_is32 = 1;
}

__global__ void convert_kernel(const void* __restrict__ ei, int E, int Nn) {
    int e = blockIdx.x * blockDim.x + threadIdx.x;
    if (e >= E) return;
    long long s, d;
    if (g_is32) {
        const int* p = (const int*)ei;
        s = p[e]; d = p[E + e];
    } else {
        const long long* p = (const long long*)ei;
        s = p[e]; d = p[E + e];
    }
    // clamp defensively: never trap on bad data
    if (s < 0) s = 0; if (s >= Nn) s = Nn - 1;
    if (d < 0) d = 0; if (d >= Nn) d = Nn - 1;
    g_src[e] = (int)s;
    g_dst[e] = (int)d;
}

// ---------------- CSR build ----------------------------------------------
__global__ void hist_kernel(int E) {
    int i = blockIdx.x * blockDim.x + threadIdx.x;
    if (i < E) atomicAdd(&g_cnt[g_dst[i]], 1);
}

__global__ void scan1_kernel(int Nn) {
    __shared__ int s[512];
    int i = blockIdx.x * 512 + threadIdx.x;
    int v = (i < Nn) ? g_cnt[i] : 0;
    s[threadIdx.x] = v;
    __syncthreads();
#pragma unroll
    for (int off = 1; off < 512; off <<= 1) {
        int t = (threadIdx.x >= off) ? s[threadIdx.x - off] : 0;
        __syncthreads();
        s[threadIdx.x] += t;
        __syncthreads();
    }
    if (i < Nn) g_rowptr[i] = s[threadIdx.x] - v;   // exclusive
    if (threadIdx.x == 511) g_bsums[blockIdx.x] = s[511];
}

__global__ void scan2_kernel(int nb) {
    __shared__ int s[256];
    int v = (threadIdx.x < nb) ? g_bsums[threadIdx.x] : 0;
    s[threadIdx.x] = v;
    __syncthreads();
#pragma unroll
    for (int off = 1; off < 256; off <<= 1) {
        int t = (threadIdx.x >= off) ? s[threadIdx.x - off] : 0;
        __syncthreads();
        s[threadIdx.x] += t;
        __syncthreads();
    }
    g_boffs[threadIdx.x] = s[threadIdx.x] - v;      // exclusive
}

__global__ void scan3_kernel(int Nn, int E) {
    int i = blockIdx.x * blockDim.x + threadIdx.x;
    if (i < Nn) {
        int r = g_rowptr[i] + g_boffs[i >> 9];
        g_rowptr[i] = r;
        g_cursor[i] = r;
    }
    if (i == 0) g_rowptr[Nn] = E;
}

__global__ void fill_kernel(int E) {
    int e = blockIdx.x * blockDim.x + threadIdx.x;
    if (e < E) {
        int pos = atomicAdd(&g_cursor[g_dst[e]], 1);
        g_esrc[pos] = g_src[e];
    }
}

// ---------------- gather-mean aggregations -------------------------------
__global__ void agg1_kernel(const float* __restrict__ x, int Nn) {
    int warp = (blockIdx.x * blockDim.x + threadIdx.x) >> 5;
    int lane = threadIdx.x & 31;
    if (warp >= Nn) return;
    int s0 = g_rowptr[warp], s1 = g_rowptr[warp + 1];
    float4 acc = make_float4(0.f, 0.f, 0.f, 0.f);
    for (int e = s0; e < s1; e++) {
        int src = g_esrc[e];
        float4 v = *(const float4*)(x + (size_t)src * 128 + lane * 4);
        acc.x += v.x; acc.y += v.y; acc.z += v.z; acc.w += v.w;
    }
    float inv = 1.f / fmaxf((float)(s1 - s0), 1.f);
    acc.x *= inv; acc.y *= inv; acc.z *= inv; acc.w *= inv;
    *(float4*)(g_agg1 + (size_t)warp * 128 + lane * 4) = acc;
}

__global__ void agg2_kernel(int Nn) {
    int warp = (blockIdx.x * blockDim.x + threadIdx.x) >> 5;
    int lane = threadIdx.x & 31;
    if (warp >= Nn) return;
    int s0 = g_rowptr[warp], s1 = g_rowptr[warp + 1];
    float2 acc = make_float2(0.f, 0.f);
    for (int e = s0; e < s1; e++) {
        int src = g_esrc[e];
        float2 v = *(const float2*)(g_t + (size_t)src * 64 + lane * 2);
        acc.x += v.x; acc.y += v.y;
    }
    float inv = 1.f / fmaxf((float)(s1 - s0), 1.f);
    acc.x *= inv; acc.y *= inv;
    *(float2*)(g_agg2 + (size_t)warp * 64 + lane * 2) = acc;
}

// ---------------- GEMM1: h = relu([agg1 | x] @ [W1l;W1r] + b1) -----------
__global__ __launch_bounds__(256, 2)
void gemm1_kernel(const float* __restrict__ x,
                  const float* __restrict__ W1l,
                  const float* __restrict__ W1r,
                  const float* __restrict__ b1, int Nn) {
    __shared__ float As[16][132];
    __shared__ float Bs[16][128];

    const int tid = threadIdx.x;
    const int ty = tid >> 4;
    const int tx = tid & 15;
    const int m0 = blockIdx.x * 128;
    const int n0 = blockIdx.y * 128;

    const int la_f = tid & 3;
    const int la_m = tid >> 2;
    const int lb_c = tid & 31;
    const int lb_r = tid >> 5;

    float acc[8][8];
#pragma unroll
    for (int i = 0; i < 8; i++)
#pragma unroll
        for (int j = 0; j < 8; j++) acc[i][j] = 0.f;

    for (int kt = 0; kt < 256; kt += 16) {
        const bool first = (kt < 128);
        const float* Asrc = first ? (const float*)g_agg1 : x;
        const float* Bsrc = first ? W1l : W1r;
        const int kk = kt & 127;

#pragma unroll
        for (int r = 0; r < 2; r++) {
            int m = la_m + r * 64;
            int gm = m0 + m;
            float4 v = make_float4(0.f, 0.f, 0.f, 0.f);
            if (gm < Nn)
                v = *(const float4*)(Asrc + (size_t)gm * 128 + kk + la_f * 4);
            As[la_f * 4 + 0][m] = v.x;
            As[la_f * 4 + 1][m] = v.y;
            As[la_f * 4 + 2][m] = v.z;
            As[la_f * 4 + 3][m] = v.w;
        }
#pragma unroll
        for (int r = 0; r < 2; r++) {
            int row = lb_r + r * 8;
            float4 v = *(const float4*)(Bsrc + (size_t)(kk + row) * 256 + n0 + lb_c * 4);
            *(float4*)&Bs[row][lb_c * 4] = v;
        }
        __syncthreads();

#pragma unroll
        for (int k = 0; k < 16; k++) {
            float a[8], b[8];
            *(float4*)&a[0] = *(const float4*)&As[k][ty * 8];
            *(float4*)&a[4] = *(const float4*)&As[k][ty * 8 + 4];
            *(float4*)&b[0] = *(const float4*)&Bs[k][tx * 8];
            *(float4*)&b[4] = *(const float4*)&Bs[k][tx * 8 + 4];
#pragma unroll
            for (int i = 0; i < 8; i++)
#pragma unroll
                for (int j = 0; j < 8; j++)
                    acc[i][j] = fmaf(a[i], b[j], acc[i][j]);
        }
        __syncthreads();
    }

#pragma unroll
    for (int i = 0; i < 8; i++) {
        int gm = m0 + ty * 8 + i;
        if (gm < Nn) {
#pragma unroll
            for (int j0 = 0; j0 < 8; j0 += 4) {
                int n = n0 + tx * 8 + j0;
                float4 v;
                v.x = fmaxf(acc[i][j0 + 0] + b1[n + 0], 0.f);
                v.y = fmaxf(acc[i][j0 + 1] + b1[n + 1], 0.f);
                v.z = fmaxf(acc[i][j0 + 2] + b1[n + 2], 0.f);
                v.w = fmaxf(acc[i][j0 + 3] + b1[n + 3], 0.f);
                *(float4*)(g_h + (size_t)gm * 256 + n) = v;
            }
        }
    }
}

// ---------------- GEMM over h: [Nn,256] @ [256,64] -----------------------
template <int MODE>
__global__ __launch_bounds__(256, 2)
void gemm_n64_kernel(const float* __restrict__ W,
                     const float* __restrict__ bias,
                     float* __restrict__ out, int Nn) {
    __shared__ float As[16][132];
    __shared__ float Bs[16][64];

    const int tid = threadIdx.x;
    const int ty = tid >> 4;
    const int tx = tid & 15;
    const int m0 = blockIdx.x * 128;

    const int la_f = tid & 3;
    const int la_m = tid >> 2;
    const int lb_c = tid & 15;
    const int lb_r = tid >> 4;

    float acc[8][4];
#pragma unroll
    for (int i = 0; i < 8; i++)
#pragma unroll
        for (int j = 0; j < 4; j++) acc[i][j] = 0.f;

    for (int kt = 0; kt < 256; kt += 16) {
#pragma unroll
        for (int r = 0; r < 2; r++) {
            int m = la_m + r * 64;
            int gm = m0 + m;
            float4 v = make_float4(0.f, 0.f, 0.f, 0.f);
            if (gm < Nn)
                v = *(const float4*)(g_h + (size_t)gm * 256 + kt + la_f * 4);
            As[la_f * 4 + 0][m] = v.x;
            As[la_f * 4 + 1][m] = v.y;
            As[la_f * 4 + 2][m] = v.z;
            As[la_f * 4 + 3][m] = v.w;
        }
        {
            float4 v = *(const float4*)(W + (size_t)(kt + lb_r) * 64 + lb_c * 4);
            *(float4*)&Bs[lb_r][lb_c * 4] = v;
        }
        __syncthreads();

#pragma unroll
        for (int k = 0; k < 16; k++) {
            float a[8], b[4];
            *(float4*)&a[0] = *(const float4*)&As[k][ty * 8];
            *(float4*)&a[4] = *(const float4*)&As[k][ty * 8 + 4];
            *(float4*)&b[0] = *(const float4*)&Bs[k][tx * 4];
#pragma unroll
            for (int i = 0; i < 8; i++)
#pragma unroll
                for (int j = 0; j < 4; j++)
                    acc[i][j] = fmaf(a[i], b[j], acc[i][j]);
        }
        __syncthreads();
    }

#pragma unroll
    for (int i = 0; i < 8; i++) {
        int gm = m0 + ty * 8 + i;
        if (gm < Nn) {
            int n = tx * 4;
            float4 v;
            if (MODE == 0) {
                v.x = acc[i][0]; v.y = acc[i][1]; v.z = acc[i][2]; v.w = acc[i][3];
                *(float4*)(g_t + (size_t)gm * 64 + n) = v;
            } else {
                const float* a2 = g_agg2 + (size_t)gm * 64 + n;
                v.x = acc[i][0] + bias[n + 0] + a2[0];
                v.y = acc[i][1] + bias[n + 1] + a2[1];
                v.z = acc[i][2] + bias[n + 2] + a2[2];
                v.w = acc[i][3] + bias[n + 3] + a2[3];
                *(float4*)(out + (size_t)gm * 64 + n) = v;
            }
        }
    }
}

// ---------------- launch --------------------------------------------------
extern "C" void kernel_launch(void* const* d_in, const int* in_sizes, int n_in,
                              void* d_out, int out_size) {
    const float* x   = (const float*)d_in[0];
    const void*  ei  = d_in[1];                 // int32 or int64, [2, E]
    const float* W1l = (const float*)d_in[2];
    const float* b1  = (const float*)d_in[3];
    const float* W1r = (const float*)d_in[4];
    const float* W2l = (const float*)d_in[5];
    const float* b2  = (const float*)d_in[6];
    const float* W2r = (const float*)d_in[7];
    float*       out = (float*)d_out;

    const int Nn = in_sizes[0] / 128;
    const int E  = in_sizes[1] / 2;
    const int nb = (Nn + 511) / 512;

    // normalize edge list dtype
    reset_kernel<<<(Nn + 255) / 256, 256>>>(Nn);
    probe_kernel<<<(E + 255) / 256, 256>>>(ei, E, Nn);
    convert_kernel<<<(E + 255) / 256, 256>>>(ei, E, Nn);

    // CSR build
    hist_kernel<<<(E + 255) / 256, 256>>>(E);
    scan1_kernel<<<nb, 512>>>(Nn);
    scan2_kernel<<<1, 256>>>(nb);
    scan3_kernel<<<(Nn + 255) / 256, 256>>>(Nn, E);
    fill_kernel<<<(E + 255) / 256, 256>>>(E);

    // layer 1
    agg1_kernel<<<(Nn * 32 + 255) / 256, 256>>>(x, Nn);
    gemm1_kernel<<<dim3((Nn + 127) / 128, 2), 256>>>(x, W1l, W1r, b1, Nn);

    // layer 2 (mean commutes with @W2l: aggregate the 64-dim projection)
    gemm_n64_kernel<0><<<(Nn + 127) / 128, 256>>>(W2l, b2, out, Nn);
    agg2_kernel<<<(Nn * 32 + 255) / 256, 256>>>(Nn);
    gemm_n64_kernel<1><<<(Nn + 127) / 128, 256>>>(W2r, b2, out, Nn);
}

// round 5
// speedup vs baseline: 1.4199x; 1.4199x over previous
#include <cuda_runtime.h>
#include <cuda_bf16.h>
#include <cstdint>

#define N_MAX 100000
#define N_PAD 100096   // ceil to 128 so GEMM tiles never read OOB
#define E_MAX 400000

// ---------------- scratch (__device__ globals) ---------------------------
__device__ __align__(16) unsigned short g_a1hi[(size_t)N_PAD * 256];  // [agg1|x] hi
__device__ __align__(16) unsigned short g_a1lo[(size_t)N_PAD * 256];  // [agg1|x] lo
__device__ __align__(16) unsigned short g_hhi [(size_t)N_PAD * 256];  // h hi
__device__ __align__(16) unsigned short g_hlo [(size_t)N_PAD * 256];  // h lo
__device__ __align__(16) unsigned short g_W1hi[256 * 256];  // [n][k]
__device__ __align__(16) unsigned short g_W1lo[256 * 256];
__device__ __align__(16) unsigned short g_W2hi[128 * 256];  // [n][k], n = [W2l|W2r]
__device__ __align__(16) unsigned short g_W2lo[128 * 256];
__device__ __align__(16) float g_t   [(size_t)N_MAX * 64];
__device__ __align__(16) float g_o2  [(size_t)N_MAX * 64];
__device__ __align__(16) float g_agg2[(size_t)N_MAX * 64];
__device__ int g_src[E_MAX], g_dst[E_MAX], g_cnt[N_MAX];
__device__ int g_rowptr[N_MAX + 1], g_cursor[N_MAX], g_esrc[E_MAX];
__device__ int g_bsums[256], g_boffs[256], g_is32;

// ---------------- helpers --------------------------------------------------
__device__ __forceinline__ void split_bf16(float v, unsigned short& hi, unsigned short& lo) {
    __nv_bfloat16 h = __float2bfloat16(v);
    hi = __bfloat16_as_ushort(h);
    lo = __bfloat16_as_ushort(__float2bfloat16(v - __bfloat162float(h)));
}

__device__ __forceinline__ uint32_t smem_u32(const void* p) {
    uint32_t a;
    asm("{ .reg .u64 t; cvta.to.shared.u64 t, %1; cvt.u32.u64 %0, t; }" : "=r"(a) : "l"(p));
    return a;
}

__device__ __forceinline__ void cp16(uint32_t dst, const void* src) {
    asm volatile("cp.async.cg.shared.global [%0], [%1], 16;" :: "r"(dst), "l"(src) : "memory");
}
__device__ __forceinline__ void cp_commit() {
    asm volatile("cp.async.commit_group;" ::: "memory");
}
__device__ __forceinline__ void cp_wait0() {
    asm volatile("cp.async.wait_group 0;" ::: "memory");
}

__device__ __forceinline__ void ldsm_x4(uint32_t& r0, uint32_t& r1, uint32_t& r2, uint32_t& r3,
                                        uint32_t addr) {
    asm volatile("ldmatrix.sync.aligned.m8n8.x4.shared.b16 {%0,%1,%2,%3}, [%4];"
                 : "=r"(r0), "=r"(r1), "=r"(r2), "=r"(r3) : "r"(addr));
}

__device__ __forceinline__ void mma_bf16(float* c, const uint32_t* a, uint32_t b0, uint32_t b1) {
    asm volatile(
        "mma.sync.aligned.m16n8k16.row.col.f32.bf16.bf16.f32 "
        "{%0,%1,%2,%3}, {%4,%5,%6,%7}, {%8,%9}, {%0,%1,%2,%3};"
        : "+f"(c[0]), "+f"(c[1]), "+f"(c[2]), "+f"(c[3])
        : "r"(a[0]), "r"(a[1]), "r"(a[2]), "r"(a[3]), "r"(b0), "r"(b1));
}

// ---------------- edge dtype probe + normalize -----------------------------
__global__ void reset_kernel(int Nn) {
    int i = blockIdx.x * blockDim.x + threadIdx.x;
    if (i < Nn) g_cnt[i] = 0;
    if (i == 0) g_is32 = 0;
}

__global__ void probe_kernel(const void* __restrict__ ei, int E, int Nn) {
    int e = blockIdx.x * blockDim.x + threadIdx.x;
    if (e >= E) return;
    long long v = ((const long long*)ei)[e];
    if (v < 0 || v >= (long long)Nn) g_is32 = 1;
}

__global__ void convert_kernel(const void* __restrict__ ei, int E, int Nn) {
    int e = blockIdx.x * blockDim.x + threadIdx.x;
    if (e >= E) return;
    long long s, d;
    if (g_is32) {
        const int* p = (const int*)ei;
        s = p[e]; d = p[E + e];
    } else {
        const long long* p = (const long long*)ei;
        s = p[e]; d = p[E + e];
    }
    if (s < 0) s = 0; if (s >= Nn) s = Nn - 1;
    if (d < 0) d = 0; if (d >= Nn) d = Nn - 1;
    g_src[e] = (int)s;
    g_dst[e] = (int)d;
}

// ---------------- CSR build -------------------------------------------------
__global__ void hist_kernel(int E) {
    int i = blockIdx.x * blockDim.x + threadIdx.x;
    if (i < E) atomicAdd(&g_cnt[g_dst[i]], 1);
}

__global__ void scan1_kernel(int Nn) {
    __shared__ int s[512];
    int i = blockIdx.x * 512 + threadIdx.x;
    int v = (i < Nn) ? g_cnt[i] : 0;
    s[threadIdx.x] = v;
    __syncthreads();
#pragma unroll
    for (int off = 1; off < 512; off <<= 1) {
        int t = (threadIdx.x >= off) ? s[threadIdx.x - off] : 0;
        __syncthreads();
        s[threadIdx.x] += t;
        __syncthreads();
    }
    if (i < Nn) g_rowptr[i] = s[threadIdx.x] - v;
    if (threadIdx.x == 511) g_bsums[blockIdx.x] = s[511];
}

__global__ void scan2_kernel(int nb) {
    __shared__ int s[256];
    int v = (threadIdx.x < nb) ? g_bsums[threadIdx.x] : 0;
    s[threadIdx.x] = v;
    __syncthreads();
#pragma unroll
    for (int off = 1; off < 256; off <<= 1) {
        int t = (threadIdx.x >= off) ? s[threadIdx.x - off] : 0;
        __syncthreads();
        s[threadIdx.x] += t;
        __syncthreads();
    }
    g_boffs[threadIdx.x] = s[threadIdx.x] - v;
}

__global__ void scan3_kernel(int Nn, int E) {
    int i = blockIdx.x * blockDim.x + threadIdx.x;
    if (i < Nn) {
        int r = g_rowptr[i] + g_boffs[i >> 9];
        g_rowptr[i] = r;
        g_cursor[i] = r;
    }
    if (i == 0) g_rowptr[Nn] = E;
}

__global__ void fill_kernel(int E) {
    int e = blockIdx.x * blockDim.x + threadIdx.x;
    if (e < E) {
        int pos = atomicAdd(&g_cursor[g_dst[e]], 1);
        g_esrc[pos] = g_src[e];
    }
}

// ---------------- gather-mean agg1 (split bf16, cols 0..127) ----------------
__global__ void agg1_kernel(const float* __restrict__ x, int Nn) {
    int warp = (blockIdx.x * blockDim.x + threadIdx.x) >> 5;
    int lane = threadIdx.x & 31;
    if (warp >= Nn) return;
    int s0 = g_rowptr[warp], s1 = g_rowptr[warp + 1];
    float4 acc = make_float4(0.f, 0.f, 0.f, 0.f);
    for (int e = s0; e < s1; e++) {
        int src = g_esrc[e];
        float4 v = *(const float4*)(x + (size_t)src * 128 + lane * 4);
        acc.x += v.x; acc.y += v.y; acc.z += v.z; acc.w += v.w;
    }
    float inv = 1.f / fmaxf((float)(s1 - s0), 1.f);
    acc.x *= inv; acc.y *= inv; acc.z *= inv; acc.w *= inv;
    unsigned short h0, h1, h2, h3, l0, l1, l2, l3;
    split_bf16(acc.x, h0, l0); split_bf16(acc.y, h1, l1);
    split_bf16(acc.z, h2, l2); split_bf16(acc.w, h3, l3);
    uint2 hv = make_uint2((uint32_t)h0 | ((uint32_t)h1 << 16),
                          (uint32_t)h2 | ((uint32_t)h3 << 16));
    uint2 lv = make_uint2((uint32_t)l0 | ((uint32_t)l1 << 16),
                          (uint32_t)l2 | ((uint32_t)l3 << 16));
    *(uint2*)(g_a1hi + (size_t)warp * 256 + lane * 4) = hv;
    *(uint2*)(g_a1lo + (size_t)warp * 256 + lane * 4) = lv;
}

// ---------------- x -> split bf16 (cols 128..255) ----------------------------
__global__ void xconv_kernel(const float* __restrict__ x, int Nn) {
    int gid = blockIdx.x * blockDim.x + threadIdx.x;
    if (gid >= Nn * 32) return;
    int node = gid >> 5;
    int c = (gid & 31) * 4;
    float4 v = *(const float4*)(x + (size_t)node * 128 + c);
    unsigned short h0, h1, h2, h3, l0, l1, l2, l3;
    split_bf16(v.x, h0, l0); split_bf16(v.y, h1, l1);
    split_bf16(v.z, h2, l2); split_bf16(v.w, h3, l3);
    uint2 hv = make_uint2((uint32_t)h0 | ((uint32_t)h1 << 16),
                          (uint32_t)h2 | ((uint32_t)h3 << 16));
    uint2 lv = make_uint2((uint32_t)l0 | ((uint32_t)l1 << 16),
                          (uint32_t)l2 | ((uint32_t)l3 << 16));
    *(uint2*)(g_a1hi + (size_t)node * 256 + 128 + c) = hv;
    *(uint2*)(g_a1lo + (size_t)node * 256 + 128 + c) = lv;
}

// ---------------- weight transpose + split -----------------------------------
__global__ void w1conv_kernel(const float* __restrict__ W1l, const float* __restrict__ W1r) {
    int gid = blockIdx.x * blockDim.x + threadIdx.x;
    if (gid >= 256 * 256) return;
    int n = gid & 255, k = gid >> 8;
    float v = (k < 128) ? W1l[(size_t)k * 256 + n] : W1r[(size_t)(k - 128) * 256 + n];
    unsigned short h, l;
    split_bf16(v, h, l);
    g_W1hi[n * 256 + k] = h;
    g_W1lo[n * 256 + k] = l;
}

__global__ void w2conv_kernel(const float* __restrict__ W2l, const float* __restrict__ W2r) {
    int gid = blockIdx.x * blockDim.x + threadIdx.x;
    if (gid >= 128 * 256) return;
    int n = gid & 127, k = gid >> 7;
    float v = (n < 64) ? W2l[(size_t)k * 64 + n] : W2r[(size_t)k * 64 + (n - 64)];
    unsigned short h, l;
    split_bf16(v, h, l);
    g_W2hi[n * 256 + k] = h;
    g_W2lo[n * 256 + k] = l;
}

// ---------------- HMMA split-bf16 GEMM ---------------------------------------
// SMEM tile: 128 rows x 64 bf16, padded row stride 144B (conflict-free ldmatrix).
#define ROWB 144
#define TILE_BYTES (128 * ROWB)   // 18432

__device__ __forceinline__ void load_tile(uint32_t sA, uint32_t sB,
                                          const unsigned short* __restrict__ A,
                                          const unsigned short* __restrict__ B,
                                          int m0, int nB0, int k0, int tid) {
    int row = tid >> 1;
    const char* srcA = (const char*)(A + (size_t)(m0 + row) * 256 + k0);
    const char* srcB = (const char*)(B + (size_t)(nB0 + row) * 256 + k0);
    uint32_t dA = sA + row * ROWB + (tid & 1) * 64;
    uint32_t dB = sB + row * ROWB + (tid & 1) * 64;
    const char* sA4 = srcA + (tid & 1) * 64;
    const char* sB4 = srcB + (tid & 1) * 64;
#pragma unroll
    for (int j = 0; j < 4; j++) {
        cp16(dA + j * 16, sA4 + j * 16);
        cp16(dB + j * 16, sB4 + j * 16);
    }
}

// MODE 1: D[.,256] = [agg1|x] @ W1cat ; +b1, relu, split -> g_hhi/g_hlo
// MODE 2: D[.,128] = h @ [W2l|W2r]    ; fp32 -> g_t (n<64) / g_o2 (n>=64)
template <int MODE>
__global__ __launch_bounds__(256, 2)
void mma_kernel(const float* __restrict__ bias, int Nn) {
    extern __shared__ char sm[];
    const uint32_t smb = smem_u32(sm);
    const uint32_t A0 = smb, A1 = smb + TILE_BYTES;
    const uint32_t B0 = smb + 2 * TILE_BYTES, B1 = smb + 3 * TILE_BYTES;

    const int tid = threadIdx.x;
    const int wid = tid >> 5;
    const int lane = tid & 31;
    const int m0 = blockIdx.x * 128;
    const int n0 = blockIdx.y * 128;      // 0 for MODE 2

    const unsigned short* Ahi = (MODE == 1) ? g_a1hi : g_hhi;
    const unsigned short* Alo = (MODE == 1) ? g_a1lo : g_hlo;
    const unsigned short* Bhi = (MODE == 1) ? g_W1hi : g_W2hi;
    const unsigned short* Blo = (MODE == 1) ? g_W1lo : g_W2lo;

    const int wm = (wid >> 2) * 64;
    const int wn = (wid & 3) * 32;
    const int lrow = lane & 15;
    const int lcol8 = (lane >> 4) * 8;

    float acc[4][4][4];
#pragma unroll
    for (int i = 0; i < 4; i++)
#pragma unroll
        for (int j = 0; j < 4; j++)
#pragma unroll
            for (int q = 0; q < 4; q++) acc[i][j][q] = 0.f;

    // prologue
    load_tile(A0, B0, Ahi, Bhi, m0, n0, 0, tid);
    cp_commit();
    cp_wait0();
    __syncthreads();

    for (int it = 0; it < 12; it++) {
        if (it + 1 < 12) {
            int t = (it + 1) >> 2;             // term: 0 hi*hi, 1 lo*hi, 2 hi*lo
            int k0 = ((it + 1) & 3) * 64;
            const unsigned short* A = (t == 1) ? Alo : Ahi;
            const unsigned short* B = (t == 2) ? Blo : Bhi;
            load_tile(((it + 1) & 1) ? A1 : A0, ((it + 1) & 1) ? B1 : B0,
                      A, B, m0, n0, k0, tid);
            cp_commit();
        }
        uint32_t sA = (it & 1) ? A1 : A0;
        uint32_t sB = (it & 1) ? B1 : B0;
#pragma unroll
        for (int ks = 0; ks < 4; ks++) {
            int kb = ks * 16 + lcol8;
            uint32_t a[4][4], b[2][4];
#pragma unroll
            for (int mt = 0; mt < 4; mt++)
                ldsm_x4(a[mt][0], a[mt][1], a[mt][2], a[mt][3],
                        sA + (wm + mt * 16 + lrow) * ROWB + kb * 2);
#pragma unroll
            for (int p = 0; p < 2; p++)
                ldsm_x4(b[p][0], b[p][1], b[p][2], b[p][3],
                        sB + (wn + p * 16 + lrow) * ROWB + kb * 2);
#pragma unroll
            for (int mt = 0; mt < 4; mt++)
#pragma unroll
                for (int nt = 0; nt < 4; nt++)
                    mma_bf16(acc[mt][nt], a[mt], b[nt >> 1][nt & 1], b[nt >> 1][(nt & 1) + 2]);
        }
        if (it + 1 < 12) cp_wait0();
        __syncthreads();
    }

    // epilogue
#pragma unroll
    for (int mt = 0; mt < 4; mt++) {
        int r0 = m0 + wm + mt * 16 + (lane >> 2);
#pragma unroll
        for (int nt = 0; nt < 4; nt++) {
            int colL = wn + nt * 8 + (lane & 3) * 2;       // local col (pair)
            if (MODE == 1) {
                int col = n0 + colL;
                float bb0 = __ldg(bias + col), bb1 = __ldg(bias + col + 1);
#pragma unroll
                for (int h = 0; h < 2; h++) {
                    int r = r0 + h * 8;
                    if (r < Nn) {
                        float v0 = fmaxf(acc[mt][nt][2 * h + 0] + bb0, 0.f);
                        float v1 = fmaxf(acc[mt][nt][2 * h + 1] + bb1, 0.f);
                        unsigned short h0, l0, h1, l1;
                        split_bf16(v0, h0, l0);
                        split_bf16(v1, h1, l1);
                        *(uint32_t*)(g_hhi + (size_t)r * 256 + col) =
                            (uint32_t)h0 | ((uint32_t)h1 << 16);
                        *(uint32_t*)(g_hlo + (size_t)r * 256 + col) =
                            (uint32_t)l0 | ((uint32_t)l1 << 16);
                    }
                }
            } else {
#pragma unroll
                for (int h = 0; h < 2; h++) {
                    int r = r0 + h * 8;
                    if (r < Nn) {
                        float2 v = make_float2(acc[mt][nt][2 * h + 0], acc[mt][nt][2 * h + 1]);
                        if (colL < 64)
                            *(float2*)(g_t + (size_t)r * 64 + colL) = v;
                        else
                            *(float2*)(g_o2 + (size_t)r * 64 + (colL - 64)) = v;
                    }
                }
            }
        }
    }
}

// ---------------- gather-mean agg2 over g_t ----------------------------------
__global__ void agg2_kernel(int Nn) {
    int warp = (blockIdx.x * blockDim.x + threadIdx.x) >> 5;
    int lane = threadIdx.x & 31;
    if (warp >= Nn) return;
    int s0 = g_rowptr[warp], s1 = g_rowptr[warp + 1];
    float2 acc = make_float2(0.f, 0.f);
    for (int e = s0; e < s1; e++) {
        int src = g_esrc[e];
        float2 v = *(const float2*)(g_t + (size_t)src * 64 + lane * 2);
        acc.x += v.x; acc.y += v.y;
    }
    float inv = 1.f / fmaxf((float)(s1 - s0), 1.f);
    acc.x *= inv; acc.y *= inv;
    *(float2*)(g_agg2 + (size_t)warp * 64 + lane * 2) = acc;
}

// ---------------- final: out = g_o2 + b2 + g_agg2 -----------------------------
__global__ void final_add_kernel(const float* __restrict__ b2,
                                 float* __restrict__ out, int Nn) {
    int gid = blockIdx.x * blockDim.x + threadIdx.x;
    if (gid >= Nn * 16) return;
    int node = gid >> 4;
    int c = (gid & 15) * 4;
    float4 a = *(const float4*)(g_o2 + (size_t)node * 64 + c);
    float4 g = *(const float4*)(g_agg2 + (size_t)node * 64 + c);
    float4 b = *(const float4*)(b2 + c);
    float4 v = make_float4(a.x + g.x + b.x, a.y + g.y + b.y,
                           a.z + g.z + b.z, a.w + g.w + b.w);
    *(float4*)(out + (size_t)node * 64 + c) = v;
}

// ---------------- launch -------------------------------------------------------
extern "C" void kernel_launch(void* const* d_in, const int* in_sizes, int n_in,
                              void* d_out, int out_size) {
    const float* x   = (const float*)d_in[0];
    const void*  ei  = d_in[1];
    const float* W1l = (const float*)d_in[2];
    const float* b1  = (const float*)d_in[3];
    const float* W1r = (const float*)d_in[4];
    const float* W2l = (const float*)d_in[5];
    const float* b2  = (const float*)d_in[6];
    const float* W2r = (const float*)d_in[7];
    float*       out = (float*)d_out;

    const int Nn = in_sizes[0] / 128;
    const int E  = in_sizes[1] / 2;
    const int nb = (Nn + 511) / 512;

    const int SMEM = 4 * TILE_BYTES;   // 73728
    cudaFuncSetAttribute(mma_kernel<1>, cudaFuncAttributeMaxDynamicSharedMemorySize, SMEM);
    cudaFuncSetAttribute(mma_kernel<2>, cudaFuncAttributeMaxDynamicSharedMemorySize, SMEM);

    // edge dtype normalize + CSR
    reset_kernel<<<(Nn + 255) / 256, 256>>>(Nn);
    probe_kernel<<<(E + 255) / 256, 256>>>(ei, E, Nn);
    convert_kernel<<<(E + 255) / 256, 256>>>(ei, E, Nn);
    hist_kernel<<<(E + 255) / 256, 256>>>(E);
    scan1_kernel<<<nb, 512>>>(Nn);
    scan2_kernel<<<1, 256>>>(nb);
    scan3_kernel<<<(Nn + 255) / 256, 256>>>(Nn, E);
    fill_kernel<<<(E + 255) / 256, 256>>>(E);

    // conversions + aggregation
    w1conv_kernel<<<(256 * 256 + 255) / 256, 256>>>(W1l, W1r);
    w2conv_kernel<<<(128 * 256 + 255) / 256, 256>>>(W2l, W2r);
    xconv_kernel<<<(Nn * 32 + 255) / 256, 256>>>(x, Nn);
    agg1_kernel<<<(Nn * 32 + 255) / 256, 256>>>(x, Nn);

    const int grid = (Nn + 127) / 128;
    // layer 1: h = relu([agg1|x] @ W1cat + b1)
    mma_kernel<1><<<dim3(grid, 2), 256, SMEM>>>(b1, Nn);
    // layer 2 fused: [t | o2] = h @ [W2l | W2r]
    mma_kernel<2><<<dim3(grid, 1), 256, SMEM>>>(b2, Nn);
    // aggregate t, then out = o2 + b2 + agg2
    agg2_kernel<<<(Nn * 32 + 255) / 256, 256>>>(Nn);
    final_add_kernel<<<(Nn * 16 + 255) / 256, 256>>>(b2, out, Nn);
}

// round 6
// speedup vs baseline: 1.5862x; 1.1171x over previous
#include <cuda_runtime.h>
#include <cuda_bf16.h>
#include <cstdint>

#define N_MAX 100000
#define N_PAD 100096
#define E_MAX 400000

// ---------------- scratch ---------------------------------------------------
__device__ __align__(16) unsigned short g_a1hi[(size_t)N_PAD * 256];
__device__ __align__(16) unsigned short g_a1lo[(size_t)N_PAD * 256];
__device__ __align__(16) unsigned short g_hhi [(size_t)N_PAD * 256];
__device__ __align__(16) unsigned short g_hlo [(size_t)N_PAD * 256];
__device__ __align__(16) unsigned short g_W1hi[256 * 256];
__device__ __align__(16) unsigned short g_W1lo[256 * 256];
__device__ __align__(16) unsigned short g_W2hi[128 * 256];
__device__ __align__(16) unsigned short g_W2lo[128 * 256];
__device__ __align__(16) float g_t [(size_t)N_MAX * 64];
__device__ __align__(16) float g_o2[(size_t)N_MAX * 64];
__device__ int g_src[E_MAX], g_dst[E_MAX], g_cnt[N_MAX];
__device__ int g_rowptr[N_MAX + 1], g_cursor[N_MAX], g_esrc[E_MAX];
__device__ int g_bsums[256], g_boffs[256], g_is32;

// ---------------- helpers ---------------------------------------------------
__device__ __forceinline__ void split_bf16(float v, unsigned short& hi, unsigned short& lo) {
    __nv_bfloat16 h = __float2bfloat16(v);
    hi = __bfloat16_as_ushort(h);
    lo = __bfloat16_as_ushort(__float2bfloat16(v - __bfloat162float(h)));
}

__device__ __forceinline__ uint32_t smem_u32(const void* p) {
    uint32_t a;
    asm("{ .reg .u64 t; cvta.to.shared.u64 t, %1; cvt.u32.u64 %0, t; }" : "=r"(a) : "l"(p));
    return a;
}

__device__ __forceinline__ void cp16(uint32_t dst, const void* src) {
    asm volatile("cp.async.cg.shared.global [%0], [%1], 16;" :: "r"(dst), "l"(src) : "memory");
}
__device__ __forceinline__ void cp_commit() {
    asm volatile("cp.async.commit_group;" ::: "memory");
}
__device__ __forceinline__ void cp_wait0() {
    asm volatile("cp.async.wait_group 0;" ::: "memory");
}

__device__ __forceinline__ void ldsm_x4(uint32_t& r0, uint32_t& r1, uint32_t& r2, uint32_t& r3,
                                        uint32_t addr) {
    asm volatile("ldmatrix.sync.aligned.m8n8.x4.shared.b16 {%0,%1,%2,%3}, [%4];"
                 : "=r"(r0), "=r"(r1), "=r"(r2), "=r"(r3) : "r"(addr));
}

__device__ __forceinline__ void mma_bf16(float* c, const uint32_t* a, uint32_t b0, uint32_t b1) {
    asm volatile(
        "mma.sync.aligned.m16n8k16.row.col.f32.bf16.bf16.f32 "
        "{%0,%1,%2,%3}, {%4,%5,%6,%7}, {%8,%9}, {%0,%1,%2,%3};"
        : "+f"(c[0]), "+f"(c[1]), "+f"(c[2]), "+f"(c[3])
        : "r"(a[0]), "r"(a[1]), "r"(a[2]), "r"(a[3]), "r"(b0), "r"(b1));
}

// ---------------- edge dtype probe + normalize -------------------------------
__global__ void reset_kernel(int Nn) {
    int i = blockIdx.x * blockDim.x + threadIdx.x;
    if (i < Nn) g_cnt[i] = 0;
    if (i == 0) g_is32 = 0;
}

__global__ void probe_kernel(const void* __restrict__ ei, int E, int Nn) {
    int e = blockIdx.x * blockDim.x + threadIdx.x;
    if (e >= E) return;
    long long v = ((const long long*)ei)[e];
    if (v < 0 || v >= (long long)Nn) g_is32 = 1;
}

// convert + histogram fused
__global__ void convert_hist_kernel(const void* __restrict__ ei, int E, int Nn) {
    int e = blockIdx.x * blockDim.x + threadIdx.x;
    if (e >= E) return;
    long long s, d;
    if (g_is32) {
        const int* p = (const int*)ei;
        s = p[e]; d = p[E + e];
    } else {
        const long long* p = (const long long*)ei;
        s = p[e]; d = p[E + e];
    }
    if (s < 0) s = 0; if (s >= Nn) s = Nn - 1;
    if (d < 0) d = 0; if (d >= Nn) d = Nn - 1;
    g_src[e] = (int)s;
    g_dst[e] = (int)d;
    atomicAdd(&g_cnt[(int)d], 1);
}

// ---------------- CSR scan + fill --------------------------------------------
__global__ void scan1_kernel(int Nn) {
    __shared__ int s[512];
    int i = blockIdx.x * 512 + threadIdx.x;
    int v = (i < Nn) ? g_cnt[i] : 0;
    s[threadIdx.x] = v;
    __syncthreads();
#pragma unroll
    for (int off = 1; off < 512; off <<= 1) {
        int t = (threadIdx.x >= off) ? s[threadIdx.x - off] : 0;
        __syncthreads();
        s[threadIdx.x] += t;
        __syncthreads();
    }
    if (i < Nn) g_rowptr[i] = s[threadIdx.x] - v;
    if (threadIdx.x == 511) g_bsums[blockIdx.x] = s[511];
}

__global__ void scan2_kernel(int nb) {
    __shared__ int s[256];
    int v = (threadIdx.x < nb) ? g_bsums[threadIdx.x] : 0;
    s[threadIdx.x] = v;
    __syncthreads();
#pragma unroll
    for (int off = 1; off < 256; off <<= 1) {
        int t = (threadIdx.x >= off) ? s[threadIdx.x - off] : 0;
        __syncthreads();
        s[threadIdx.x] += t;
        __syncthreads();
    }
    g_boffs[threadIdx.x] = s[threadIdx.x] - v;
}

__global__ void scan3_kernel(int Nn, int E) {
    int i = blockIdx.x * blockDim.x + threadIdx.x;
    if (i < Nn) {
        int r = g_rowptr[i] + g_boffs[i >> 9];
        g_rowptr[i] = r;
        g_cursor[i] = r;
    }
    if (i == 0) g_rowptr[Nn] = E;
}

__global__ void fill_kernel(int E) {
    int e = blockIdx.x * blockDim.x + threadIdx.x;
    if (e < E) {
        int pos = atomicAdd(&g_cursor[g_dst[e]], 1);
        g_esrc[pos] = g_src[e];
    }
}

// ---------------- fused conversions: W1, W2, x -------------------------------
__global__ void conv_all_kernel(const float* __restrict__ W1l, const float* __restrict__ W1r,
                                const float* __restrict__ W2l, const float* __restrict__ W2r,
                                const float* __restrict__ x, int Nn) {
    int gid = blockIdx.x * blockDim.x + threadIdx.x;
    if (gid < 65536) {                       // W1: [n][k] transposed split
        int n = gid & 255, k = gid >> 8;
        float v = (k < 128) ? W1l[(size_t)k * 256 + n] : W1r[(size_t)(k - 128) * 256 + n];
        unsigned short h, l;
        split_bf16(v, h, l);
        g_W1hi[n * 256 + k] = h;
        g_W1lo[n * 256 + k] = l;
    } else if (gid < 98304) {                // W2: n = [W2l|W2r]
        int g = gid - 65536;
        int n = g & 127, k = g >> 7;
        float v = (n < 64) ? W2l[(size_t)k * 64 + n] : W2r[(size_t)k * 64 + (n - 64)];
        unsigned short h, l;
        split_bf16(v, h, l);
        g_W2hi[n * 256 + k] = h;
        g_W2lo[n * 256 + k] = l;
    } else {                                 // x -> split, cols 128..255 of A1
        int g = gid - 98304;
        if (g >= Nn * 32) return;
        int node = g >> 5;
        int c = (g & 31) * 4;
        float4 v = *(const float4*)(x + (size_t)node * 128 + c);
        unsigned short h0, h1, h2, h3, l0, l1, l2, l3;
        split_bf16(v.x, h0, l0); split_bf16(v.y, h1, l1);
        split_bf16(v.z, h2, l2); split_bf16(v.w, h3, l3);
        uint2 hv = make_uint2((uint32_t)h0 | ((uint32_t)h1 << 16),
                              (uint32_t)h2 | ((uint32_t)h3 << 16));
        uint2 lv = make_uint2((uint32_t)l0 | ((uint32_t)l1 << 16),
                              (uint32_t)l2 | ((uint32_t)l3 << 16));
        *(uint2*)(g_a1hi + (size_t)node * 256 + 128 + c) = hv;
        *(uint2*)(g_a1lo + (size_t)node * 256 + 128 + c) = lv;
    }
}

// ---------------- gather-mean agg1 (split bf16, cols 0..127) ------------------
__global__ void agg1_kernel(const float* __restrict__ x, int Nn) {
    int warp = (blockIdx.x * blockDim.x + threadIdx.x) >> 5;
    int lane = threadIdx.x & 31;
    if (warp >= Nn) return;
    int s0 = g_rowptr[warp], s1 = g_rowptr[warp + 1];
    float4 acc = make_float4(0.f, 0.f, 0.f, 0.f);
    for (int e = s0; e < s1; e++) {
        int src = g_esrc[e];
        float4 v = *(const float4*)(x + (size_t)src * 128 + lane * 4);
        acc.x += v.x; acc.y += v.y; acc.z += v.z; acc.w += v.w;
    }
    float inv = 1.f / fmaxf((float)(s1 - s0), 1.f);
    acc.x *= inv; acc.y *= inv; acc.z *= inv; acc.w *= inv;
    unsigned short h0, h1, h2, h3, l0, l1, l2, l3;
    split_bf16(acc.x, h0, l0); split_bf16(acc.y, h1, l1);
    split_bf16(acc.z, h2, l2); split_bf16(acc.w, h3, l3);
    uint2 hv = make_uint2((uint32_t)h0 | ((uint32_t)h1 << 16),
                          (uint32_t)h2 | ((uint32_t)h3 << 16));
    uint2 lv = make_uint2((uint32_t)l0 | ((uint32_t)l1 << 16),
                          (uint32_t)l2 | ((uint32_t)l3 << 16));
    *(uint2*)(g_a1hi + (size_t)warp * 256 + lane * 4) = hv;
    *(uint2*)(g_a1lo + (size_t)warp * 256 + lane * 4) = lv;
}

// ---------------- HMMA split-bf16 GEMM ----------------------------------------
#define ROWB 144
#define TILE_BYTES (128 * ROWB)

// load one 128x64 bf16 tile (K-major rows, stride 256 bf16) into padded SMEM
__device__ __forceinline__ void load_one(uint32_t sT, const unsigned short* __restrict__ T,
                                         int row0, int k0, int tid) {
    int row = tid >> 1;
    const char* src = (const char*)(T + (size_t)(row0 + row) * 256 + k0) + (tid & 1) * 64;
    uint32_t d = sT + row * ROWB + (tid & 1) * 64;
#pragma unroll
    for (int j = 0; j < 4; j++) cp16(d + j * 16, src + j * 16);
}

// Term schedule per k-chunk c: step0 Alo*Bhi, step1 Ahi*Bhi, step2 Ahi*Blo.
// A changes at phases 0,1; B changes at phases 0,2 -> 4 tile loads/chunk not 6.
// MODE 1: D[.,256] = [agg1|x] @ W1cat ; +b1, relu, split -> g_hhi/g_hlo
// MODE 2: D[.,128] = h @ [W2l|W2r]    ; fp32 -> g_t (n<64) / g_o2 (n>=64)
template <int MODE>
__global__ __launch_bounds__(256, 2)
void mma_kernel(const float* __restrict__ bias, int Nn) {
    extern __shared__ char sm[];
    const uint32_t smb = smem_u32(sm);
    const uint32_t Abuf[2] = { smb, smb + TILE_BYTES };
    const uint32_t Bbuf[2] = { smb + 2 * TILE_BYTES, smb + 3 * TILE_BYTES };

    const int tid = threadIdx.x;
    const int wid = tid >> 5;
    const int lane = tid & 31;
    const int m0 = blockIdx.x * 128;
    const int n0 = blockIdx.y * 128;

    const unsigned short* Ahi = (MODE == 1) ? g_a1hi : g_hhi;
    const unsigned short* Alo = (MODE == 1) ? g_a1lo : g_hlo;
    const unsigned short* Bhi = (MODE == 1) ? g_W1hi : g_W2hi;
    const unsigned short* Blo = (MODE == 1) ? g_W1lo : g_W2lo;

    const int wm = (wid >> 2) * 64;
    const int wn = (wid & 3) * 32;
    const int lrow = lane & 15;
    const int lcol8 = (lane >> 4) * 8;

    float acc[4][4][4];
#pragma unroll
    for (int i = 0; i < 4; i++)
#pragma unroll
        for (int j = 0; j < 4; j++)
#pragma unroll
            for (int q = 0; q < 4; q++) acc[i][j][q] = 0.f;

    // prologue: step 0 tiles (A = Alo chunk0, B = Bhi chunk0)
    load_one(Abuf[0], Alo, m0, 0, tid);
    load_one(Bbuf[0], Bhi, n0, 0, tid);
    cp_commit();
    cp_wait0();
    __syncthreads();

    int curA = 0, curB = 0;
    for (int s = 0; s < 12; s++) {
        int sn = s + 1;
        bool chgA = false, chgB = false;
        if (sn < 12) {
            int cn = sn / 3, pn = sn % 3;
            chgA = (pn != 2);
            chgB = (pn != 1);
            if (chgA) load_one(Abuf[curA ^ 1], (pn == 0) ? Alo : Ahi, m0, cn * 64, tid);
            if (chgB) load_one(Bbuf[curB ^ 1], (pn == 0) ? Bhi : Blo, n0, cn * 64, tid);
            cp_commit();
        }
        uint32_t sA = Abuf[curA], sB = Bbuf[curB];
#pragma unroll
        for (int ks = 0; ks < 4; ks++) {
            int kb = ks * 16 + lcol8;
            uint32_t a[4][4], b[2][4];
#pragma unroll
            for (int mt = 0; mt < 4; mt++)
                ldsm_x4(a[mt][0], a[mt][1], a[mt][2], a[mt][3],
                        sA + (wm + mt * 16 + lrow) * ROWB + kb * 2);
#pragma unroll
            for (int p = 0; p < 2; p++)
                ldsm_x4(b[p][0], b[p][1], b[p][2], b[p][3],
                        sB + (wn + p * 16 + lrow) * ROWB + kb * 2);
#pragma unroll
            for (int mt = 0; mt < 4; mt++)
#pragma unroll
                for (int nt = 0; nt < 4; nt++)
                    mma_bf16(acc[mt][nt], a[mt], b[nt >> 1][nt & 1], b[nt >> 1][(nt & 1) + 2]);
        }
        if (sn < 12) cp_wait0();
        __syncthreads();
        if (chgA) curA ^= 1;
        if (chgB) curB ^= 1;
    }

    // epilogue
#pragma unroll
    for (int mt = 0; mt < 4; mt++) {
        int r0 = m0 + wm + mt * 16 + (lane >> 2);
#pragma unroll
        for (int nt = 0; nt < 4; nt++) {
            int colL = wn + nt * 8 + (lane & 3) * 2;
            if (MODE == 1) {
                int col = n0 + colL;
                float bb0 = __ldg(bias + col), bb1 = __ldg(bias + col + 1);
#pragma unroll
                for (int h = 0; h < 2; h++) {
                    int r = r0 + h * 8;
                    if (r < Nn) {
                        float v0 = fmaxf(acc[mt][nt][2 * h + 0] + bb0, 0.f);
                        float v1 = fmaxf(acc[mt][nt][2 * h + 1] + bb1, 0.f);
                        unsigned short h0, l0, h1, l1;
                        split_bf16(v0, h0, l0);
                        split_bf16(v1, h1, l1);
                        *(uint32_t*)(g_hhi + (size_t)r * 256 + col) =
                            (uint32_t)h0 | ((uint32_t)h1 << 16);
                        *(uint32_t*)(g_hlo + (size_t)r * 256 + col) =
                            (uint32_t)l0 | ((uint32_t)l1 << 16);
                    }
                }
            } else {
#pragma unroll
                for (int h = 0; h < 2; h++) {
                    int r = r0 + h * 8;
                    if (r < Nn) {
                        float2 v = make_float2(acc[mt][nt][2 * h + 0], acc[mt][nt][2 * h + 1]);
                        if (colL < 64)
                            *(float2*)(g_t + (size_t)r * 64 + colL) = v;
                        else
                            *(float2*)(g_o2 + (size_t)r * 64 + (colL - 64)) = v;
                    }
                }
            }
        }
    }
}

// ---------------- agg2 + final fused: out = o2 + b2 + mean(gather t) ----------
__global__ void agg2_final_kernel(const float* __restrict__ b2,
                                  float* __restrict__ out, int Nn) {
    int warp = (blockIdx.x * blockDim.x + threadIdx.x) >> 5;
    int lane = threadIdx.x & 31;
    if (warp >= Nn) return;
    int s0 = g_rowptr[warp], s1 = g_rowptr[warp + 1];
    float2 acc = make_float2(0.f, 0.f);
    for (int e = s0; e < s1; e++) {
        int src = g_esrc[e];
        float2 v = *(const float2*)(g_t + (size_t)src * 64 + lane * 2);
        acc.x += v.x; acc.y += v.y;
    }
    float inv = 1.f / fmaxf((float)(s1 - s0), 1.f);
    float2 o = *(const float2*)(g_o2 + (size_t)warp * 64 + lane * 2);
    float2 bb = *(const float2*)(b2 + lane * 2);
    float2 v = make_float2(acc.x * inv + o.x + bb.x, acc.y * inv + o.y + bb.y);
    *(float2*)(out + (size_t)warp * 64 + lane * 2) = v;
}

// ---------------- launch -------------------------------------------------------
extern "C" void kernel_launch(void* const* d_in, const int* in_sizes, int n_in,
                              void* d_out, int out_size) {
    const float* x   = (const float*)d_in[0];
    const void*  ei  = d_in[1];
    const float* W1l = (const float*)d_in[2];
    const float* b1  = (const float*)d_in[3];
    const float* W1r = (const float*)d_in[4];
    const float* W2l = (const float*)d_in[5];
    const float* b2  = (const float*)d_in[6];
    const float* W2r = (const float*)d_in[7];
    float*       out = (float*)d_out;

    const int Nn = in_sizes[0] / 128;
    const int E  = in_sizes[1] / 2;
    const int nb = (Nn + 511) / 512;

    const int SMEM = 4 * TILE_BYTES;   // 73728
    cudaFuncSetAttribute(mma_kernel<1>, cudaFuncAttributeMaxDynamicSharedMemorySize, SMEM);
    cudaFuncSetAttribute(mma_kernel<2>, cudaFuncAttributeMaxDynamicSharedMemorySize, SMEM);

    reset_kernel<<<(Nn + 255) / 256, 256>>>(Nn);
    probe_kernel<<<(E + 255) / 256, 256>>>(ei, E, Nn);
    convert_hist_kernel<<<(E + 255) / 256, 256>>>(ei, E, Nn);
    scan1_kernel<<<nb, 512>>>(Nn);
    scan2_kernel<<<1, 256>>>(nb);
    scan3_kernel<<<(Nn + 255) / 256, 256>>>(Nn, E);
    fill_kernel<<<(E + 255) / 256, 256>>>(E);

    conv_all_kernel<<<(98304 + Nn * 32 + 255) / 256, 256>>>(W1l, W1r, W2l, W2r, x, Nn);
    agg1_kernel<<<(Nn * 32 + 255) / 256, 256>>>(x, Nn);

    const int grid = (Nn + 127) / 128;
    mma_kernel<1><<<dim3(grid, 2), 256, SMEM>>>(b1, Nn);
    mma_kernel<2><<<dim3(grid, 1), 256, SMEM>>>(b2, Nn);
    agg2_final_kernel<<<(Nn * 32 + 255) / 256, 256>>>(b2, out, Nn);
}

// round 7
// speedup vs baseline: 2.1987x; 1.3862x over previous
#include <cuda_runtime.h>
#include <cuda_fp16.h>
#include <cstdint>

#define N_MAX 100000
#define N_PAD 100096
#define E_MAX 400000

// ---------------- scratch ---------------------------------------------------
__device__ __align__(16) __half g_a1 [(size_t)N_PAD * 256];   // [agg1|x] fp16
__device__ __align__(16) __half g_h  [(size_t)N_PAD * 256];   // hidden fp16
__device__ __align__(16) __half g_W1hi[256 * 256];            // [n][k]
__device__ __align__(16) __half g_W1lo[256 * 256];
__device__ __align__(16) __half g_W2hi[128 * 256];            // [n][k], n=[W2l|W2r]
__device__ __align__(16) __half g_W2lo[128 * 256];
__device__ __align__(16) float g_t [(size_t)N_MAX * 64];
__device__ __align__(16) float g_o2[(size_t)N_MAX * 64];
__device__ int g_src[E_MAX], g_dst[E_MAX], g_cnt[N_MAX];
__device__ int g_rowptr[N_MAX + 1], g_cursor[N_MAX], g_esrc[E_MAX];
__device__ int g_bsums[256], g_boffs[256], g_is32;

// ---------------- helpers ---------------------------------------------------
__device__ __forceinline__ void split_f16(float v, __half& hi, __half& lo) {
    hi = __float2half_rn(v);
    lo = __float2half_rn(v - __half2float(hi));
}

__device__ __forceinline__ uint32_t smem_u32(const void* p) {
    uint32_t a;
    asm("{ .reg .u64 t; cvta.to.shared.u64 t, %1; cvt.u32.u64 %0, t; }" : "=r"(a) : "l"(p));
    return a;
}

__device__ __forceinline__ void cp16(uint32_t dst, const void* src) {
    asm volatile("cp.async.cg.shared.global [%0], [%1], 16;" :: "r"(dst), "l"(src) : "memory");
}
__device__ __forceinline__ void cp_commit() {
    asm volatile("cp.async.commit_group;" ::: "memory");
}
__device__ __forceinline__ void cp_wait0() {
    asm volatile("cp.async.wait_group 0;" ::: "memory");
}

__device__ __forceinline__ void ldsm_x4(uint32_t& r0, uint32_t& r1, uint32_t& r2, uint32_t& r3,
                                        uint32_t addr) {
    asm volatile("ldmatrix.sync.aligned.m8n8.x4.shared.b16 {%0,%1,%2,%3}, [%4];"
                 : "=r"(r0), "=r"(r1), "=r"(r2), "=r"(r3) : "r"(addr));
}

__device__ __forceinline__ void mma_f16(float* c, const uint32_t* a, uint32_t b0, uint32_t b1) {
    asm volatile(
        "mma.sync.aligned.m16n8k16.row.col.f32.f16.f16.f32 "
        "{%0,%1,%2,%3}, {%4,%5,%6,%7}, {%8,%9}, {%0,%1,%2,%3};"
        : "+f"(c[0]), "+f"(c[1]), "+f"(c[2]), "+f"(c[3])
        : "r"(a[0]), "r"(a[1]), "r"(a[2]), "r"(a[3]), "r"(b0), "r"(b1));
}

// ---------------- edge dtype probe + normalize -------------------------------
__global__ void reset_kernel(int Nn) {
    int i = blockIdx.x * blockDim.x + threadIdx.x;
    if (i < Nn) g_cnt[i] = 0;
    if (i == 0) g_is32 = 0;
}

__global__ void probe_kernel(const void* __restrict__ ei, int E, int Nn) {
    int e = blockIdx.x * blockDim.x + threadIdx.x;
    if (e >= E) return;
    long long v = ((const long long*)ei)[e];
    if (v < 0 || v >= (long long)Nn) g_is32 = 1;
}

__global__ void convert_hist_kernel(const void* __restrict__ ei, int E, int Nn) {
    int e = blockIdx.x * blockDim.x + threadIdx.x;
    if (e >= E) return;
    long long s, d;
    if (g_is32) {
        const int* p = (const int*)ei;
        s = p[e]; d = p[E + e];
    } else {
        const long long* p = (const long long*)ei;
        s = p[e]; d = p[E + e];
    }
    if (s < 0) s = 0; if (s >= Nn) s = Nn - 1;
    if (d < 0) d = 0; if (d >= Nn) d = Nn - 1;
    g_src[e] = (int)s;
    g_dst[e] = (int)d;
    atomicAdd(&g_cnt[(int)d], 1);
}

// ---------------- CSR scan + fill --------------------------------------------
__global__ void scan1_kernel(int Nn) {
    __shared__ int s[512];
    int i = blockIdx.x * 512 + threadIdx.x;
    int v = (i < Nn) ? g_cnt[i] : 0;
    s[threadIdx.x] = v;
    __syncthreads();
#pragma unroll
    for (int off = 1; off < 512; off <<= 1) {
        int t = (threadIdx.x >= off) ? s[threadIdx.x - off] : 0;
        __syncthreads();
        s[threadIdx.x] += t;
        __syncthreads();
    }
    if (i < Nn) g_rowptr[i] = s[threadIdx.x] - v;
    if (threadIdx.x == 511) g_bsums[blockIdx.x] = s[511];
}

__global__ void scan2_kernel(int nb) {
    __shared__ int s[256];
    int v = (threadIdx.x < nb) ? g_bsums[threadIdx.x] : 0;
    s[threadIdx.x] = v;
    __syncthreads();
#pragma unroll
    for (int off = 1; off < 256; off <<= 1) {
        int t = (threadIdx.x >= off) ? s[threadIdx.x - off] : 0;
        __syncthreads();
        s[threadIdx.x] += t;
        __syncthreads();
    }
    g_boffs[threadIdx.x] = s[threadIdx.x] - v;
}

__global__ void scan3_kernel(int Nn, int E) {
    int i = blockIdx.x * blockDim.x + threadIdx.x;
    if (i < Nn) {
        int r = g_rowptr[i] + g_boffs[i >> 9];
        g_rowptr[i] = r;
        g_cursor[i] = r;
    }
    if (i == 0) g_rowptr[Nn] = E;
}

__global__ void fill_kernel(int E) {
    int e = blockIdx.x * blockDim.x + threadIdx.x;
    if (e < E) {
        int pos = atomicAdd(&g_cursor[g_dst[e]], 1);
        g_esrc[pos] = g_src[e];
    }
}

// ---------------- fused conversions: W1 split, W2 split, x -> fp16 -----------
__global__ void conv_all_kernel(const float* __restrict__ W1l, const float* __restrict__ W1r,
                                const float* __restrict__ W2l, const float* __restrict__ W2r,
                                const float* __restrict__ x, int Nn) {
    int gid = blockIdx.x * blockDim.x + threadIdx.x;
    if (gid < 65536) {                       // W1 transposed split
        int n = gid & 255, k = gid >> 8;
        float v = (k < 128) ? W1l[(size_t)k * 256 + n] : W1r[(size_t)(k - 128) * 256 + n];
        __half h, l;
        split_f16(v, h, l);
        g_W1hi[n * 256 + k] = h;
        g_W1lo[n * 256 + k] = l;
    } else if (gid < 98304) {                // W2 split, n = [W2l|W2r]
        int g = gid - 65536;
        int n = g & 127, k = g >> 7;
        float v = (n < 64) ? W2l[(size_t)k * 64 + n] : W2r[(size_t)k * 64 + (n - 64)];
        __half h, l;
        split_f16(v, h, l);
        g_W2hi[n * 256 + k] = h;
        g_W2lo[n * 256 + k] = l;
    } else {                                 // x -> fp16, cols 128..255 of A1
        int g = gid - 98304;
        if (g >= Nn * 32) return;
        int node = g >> 5;
        int c = (g & 31) * 4;
        float4 v = *(const float4*)(x + (size_t)node * 128 + c);
        __half2 p0 = __floats2half2_rn(v.x, v.y);
        __half2 p1 = __floats2half2_rn(v.z, v.w);
        *(uint2*)(g_a1 + (size_t)node * 256 + 128 + c) =
            make_uint2(*(uint32_t*)&p0, *(uint32_t*)&p1);
    }
}

// ---------------- gather-mean agg1 (fp16, cols 0..127) ------------------------
__global__ void agg1_kernel(const float* __restrict__ x, int Nn) {
    int warp = (blockIdx.x * blockDim.x + threadIdx.x) >> 5;
    int lane = threadIdx.x & 31;
    if (warp >= Nn) return;
    int s0 = g_rowptr[warp], s1 = g_rowptr[warp + 1];
    float4 acc = make_float4(0.f, 0.f, 0.f, 0.f);
    for (int e = s0; e < s1; e++) {
        int src = g_esrc[e];
        float4 v = *(const float4*)(x + (size_t)src * 128 + lane * 4);
        acc.x += v.x; acc.y += v.y; acc.z += v.z; acc.w += v.w;
    }
    float inv = 1.f / fmaxf((float)(s1 - s0), 1.f);
    __half2 p0 = __floats2half2_rn(acc.x * inv, acc.y * inv);
    __half2 p1 = __floats2half2_rn(acc.z * inv, acc.w * inv);
    *(uint2*)(g_a1 + (size_t)warp * 256 + lane * 4) =
        make_uint2(*(uint32_t*)&p0, *(uint32_t*)&p1);
}

// ---------------- HMMA fp16 weight-split GEMM ---------------------------------
#define ROWB 144
#define TILE_BYTES (128 * ROWB)

__device__ __forceinline__ void load_one(uint32_t sT, const __half* __restrict__ T,
                                         int row0, int k0, int tid) {
    int row = tid >> 1;
    const char* src = (const char*)(T + (size_t)(row0 + row) * 256 + k0) + (tid & 1) * 64;
    uint32_t d = sT + row * ROWB + (tid & 1) * 64;
#pragma unroll
    for (int j = 0; j < 4; j++) cp16(d + j * 16, src + j * 16);
}

// Schedule: per k-chunk c (4 chunks of 64): step 2c = A(c)*Blo(c), step 2c+1 = A(c)*Bhi(c).
// A changes only at even steps (4 A loads); B changes every step (8 loads, tiny+L2).
// MODE 1: D[.,256] = [agg1|x] @ W1 ; +b1, relu -> g_h (fp16)
// MODE 2: D[.,128] = h @ [W2l|W2r] ; fp32 -> g_t (n<64) / g_o2 (n>=64)
template <int MODE>
__global__ __launch_bounds__(256, 2)
void mma_kernel(const float* __restrict__ bias, int Nn) {
    extern __shared__ char sm[];
    const uint32_t smb = smem_u32(sm);
    const uint32_t Abuf[2] = { smb, smb + TILE_BYTES };
    const uint32_t Bbuf[2] = { smb + 2 * TILE_BYTES, smb + 3 * TILE_BYTES };

    const int tid = threadIdx.x;
    const int wid = tid >> 5;
    const int lane = tid & 31;
    const int m0 = blockIdx.x * 128;
    const int n0 = blockIdx.y * 128;

    const __half* A   = (MODE == 1) ? g_a1 : g_h;
    const __half* Bhi = (MODE == 1) ? g_W1hi : g_W2hi;
    const __half* Blo = (MODE == 1) ? g_W1lo : g_W2lo;

    const int wm = (wid >> 2) * 64;
    const int wn = (wid & 3) * 32;
    const int lrow = lane & 15;
    const int lcol8 = (lane >> 4) * 8;

    float acc[4][4][4];
#pragma unroll
    for (int i = 0; i < 4; i++)
#pragma unroll
        for (int j = 0; j < 4; j++)
#pragma unroll
            for (int q = 0; q < 4; q++) acc[i][j][q] = 0.f;

    // prologue: step 0 = A(0) * Blo(0)
    load_one(Abuf[0], A, m0, 0, tid);
    load_one(Bbuf[0], Blo, n0, 0, tid);
    cp_commit();
    cp_wait0();
    __syncthreads();

    int curA = 0, curB = 0;
    for (int s = 0; s < 8; s++) {
        int sn = s + 1;
        bool chgA = false;
        if (sn < 8) {
            int cn = sn >> 1, pn = sn & 1;
            chgA = (pn == 0);
            if (chgA) load_one(Abuf[curA ^ 1], A, m0, cn * 64, tid);
            load_one(Bbuf[curB ^ 1], pn ? Bhi : Blo, n0, cn * 64, tid);
            cp_commit();
        }
        uint32_t sA = Abuf[curA], sB = Bbuf[curB];
#pragma unroll
        for (int ks = 0; ks < 4; ks++) {
            int kb = ks * 16 + lcol8;
            uint32_t a[4][4], b[2][4];
#pragma unroll
            for (int mt = 0; mt < 4; mt++)
                ldsm_x4(a[mt][0], a[mt][1], a[mt][2], a[mt][3],
                        sA + (wm + mt * 16 + lrow) * ROWB + kb * 2);
#pragma unroll
            for (int p = 0; p < 2; p++)
                ldsm_x4(b[p][0], b[p][1], b[p][2], b[p][3],
                        sB + (wn + p * 16 + lrow) * ROWB + kb * 2);
#pragma unroll
            for (int mt = 0; mt < 4; mt++)
#pragma unroll
                for (int nt = 0; nt < 4; nt++)
                    mma_f16(acc[mt][nt], a[mt], b[nt >> 1][nt & 1], b[nt >> 1][(nt & 1) + 2]);
        }
        if (sn < 8) cp_wait0();
        __syncthreads();
        if (chgA) curA ^= 1;
        curB ^= 1;
    }

    // epilogue
#pragma unroll
    for (int mt = 0; mt < 4; mt++) {
        int r0 = m0 + wm + mt * 16 + (lane >> 2);
#pragma unroll
        for (int nt = 0; nt < 4; nt++) {
            int colL = wn + nt * 8 + (lane & 3) * 2;
            if (MODE == 1) {
                int col = n0 + colL;
                float bb0 = __ldg(bias + col), bb1 = __ldg(bias + col + 1);
#pragma unroll
                for (int h = 0; h < 2; h++) {
                    int r = r0 + h * 8;
                    if (r < Nn) {
                        float v0 = fmaxf(acc[mt][nt][2 * h + 0] + bb0, 0.f);
                        float v1 = fmaxf(acc[mt][nt][2 * h + 1] + bb1, 0.f);
                        __half2 p = __floats2half2_rn(v0, v1);
                        *(uint32_t*)(g_h + (size_t)r * 256 + col) = *(uint32_t*)&p;
                    }
                }
            } else {
#pragma unroll
                for (int h = 0; h < 2; h++) {
                    int r = r0 + h * 8;
                    if (r < Nn) {
                        float2 v = make_float2(acc[mt][nt][2 * h + 0], acc[mt][nt][2 * h + 1]);
                        if (colL < 64)
                            *(float2*)(g_t + (size_t)r * 64 + colL) = v;
                        else
                            *(float2*)(g_o2 + (size_t)r * 64 + (colL - 64)) = v;
                    }
                }
            }
        }
    }
}

// ---------------- agg2 + final fused: out = o2 + b2 + mean(gather t) ----------
__global__ void agg2_final_kernel(const float* __restrict__ b2,
                                  float* __restrict__ out, int Nn) {
    int warp = (blockIdx.x * blockDim.x + threadIdx.x) >> 5;
    int lane = threadIdx.x & 31;
    if (warp >= Nn) return;
    int s0 = g_rowptr[warp], s1 = g_rowptr[warp + 1];
    float2 acc = make_float2(0.f, 0.f);
    for (int e = s0; e < s1; e++) {
        int src = g_esrc[e];
        float2 v = *(const float2*)(g_t + (size_t)src * 64 + lane * 2);
        acc.x += v.x; acc.y += v.y;
    }
    float inv = 1.f / fmaxf((float)(s1 - s0), 1.f);
    float2 o = *(const float2*)(g_o2 + (size_t)warp * 64 + lane * 2);
    float2 bb = *(const float2*)(b2 + lane * 2);
    float2 v = make_float2(acc.x * inv + o.x + bb.x, acc.y * inv + o.y + bb.y);
    *(float2*)(out + (size_t)warp * 64 + lane * 2) = v;
}

// ---------------- launch -------------------------------------------------------
extern "C" void kernel_launch(void* const* d_in, const int* in_sizes, int n_in,
                              void* d_out, int out_size) {
    const float* x   = (const float*)d_in[0];
    const void*  ei  = d_in[1];
    const float* W1l = (const float*)d_in[2];
    const float* b1  = (const float*)d_in[3];
    const float* W1r = (const float*)d_in[4];
    const float* W2l = (const float*)d_in[5];
    const float* b2  = (const float*)d_in[6];
    const float* W2r = (const float*)d_in[7];
    float*       out = (float*)d_out;

    const int Nn = in_sizes[0] / 128;
    const int E  = in_sizes[1] / 2;
    const int nb = (Nn + 511) / 512;

    const int SMEM = 4 * TILE_BYTES;   // 73728
    cudaFuncSetAttribute(mma_kernel<1>, cudaFuncAttributeMaxDynamicSharedMemorySize, SMEM);
    cudaFuncSetAttribute(mma_kernel<2>, cudaFuncAttributeMaxDynamicSharedMemorySize, SMEM);

    reset_kernel<<<(Nn + 255) / 256, 256>>>(Nn);
    probe_kernel<<<(E + 255) / 256, 256>>>(ei, E, Nn);
    convert_hist_kernel<<<(E + 255) / 256, 256>>>(ei, E, Nn);
    scan1_kernel<<<nb, 512>>>(Nn);
    scan2_kernel<<<1, 256>>>(nb);
    scan3_kernel<<<(Nn + 255) / 256, 256>>>(Nn, E);
    fill_kernel<<<(E + 255) / 256, 256>>>(E);

    conv_all_kernel<<<(98304 + Nn * 32 + 255) / 256, 256>>>(W1l, W1r, W2l, W2r, x, Nn);
    agg1_kernel<<<(Nn * 32 + 255) / 256, 256>>>(x, Nn);

    const int grid = (Nn + 127) / 128;
    mma_kernel<1><<<dim3(grid, 2), 256, SMEM>>>(b1, Nn);
    mma_kernel<2><<<dim3(grid, 1), 256, SMEM>>>(b2, Nn);
    agg2_final_kernel<<<(Nn * 32 + 255) / 256, 256>>>(b2, out, Nn);
}

// round 8
// speedup vs baseline: 2.8989x; 1.3185x over previous
#include <cuda_runtime.h>
#include <cuda_fp16.h>
#include <cstdint>

#define N_MAX 100000
#define N_PAD 100096
#define E_MAX 400000

// ---------------- scratch ---------------------------------------------------
__device__ __align__(16) __half g_a1[(size_t)N_PAD * 256];   // [agg1|x] fp16
__device__ __align__(16) __half g_h [(size_t)N_PAD * 256];   // hidden fp16
__device__ __align__(16) __half g_W1[256 * 256];             // [n][k]
__device__ __align__(16) __half g_W2[128 * 256];             // [n][k], n=[W2l|W2r]
__device__ __align__(16) float g_t [(size_t)N_MAX * 64];
__device__ __align__(16) float g_o2[(size_t)N_MAX * 64];
__device__ int g_src[E_MAX], g_dst[E_MAX], g_cnt[N_MAX];
__device__ int g_rowptr[N_MAX + 1], g_cursor[N_MAX], g_esrc[E_MAX];
__device__ int g_bsums[256], g_boffs[256], g_is32;

// ---------------- helpers ---------------------------------------------------
__device__ __forceinline__ uint32_t smem_u32(const void* p) {
    uint32_t a;
    asm("{ .reg .u64 t; cvta.to.shared.u64 t, %1; cvt.u32.u64 %0, t; }" : "=r"(a) : "l"(p));
    return a;
}

__device__ __forceinline__ void cp16(uint32_t dst, const void* src) {
    asm volatile("cp.async.cg.shared.global [%0], [%1], 16;" :: "r"(dst), "l"(src) : "memory");
}
__device__ __forceinline__ void cp_commit() {
    asm volatile("cp.async.commit_group;" ::: "memory");
}
__device__ __forceinline__ void cp_wait0() {
    asm volatile("cp.async.wait_group 0;" ::: "memory");
}

__device__ __forceinline__ void ldsm_x4(uint32_t& r0, uint32_t& r1, uint32_t& r2, uint32_t& r3,
                                        uint32_t addr) {
    asm volatile("ldmatrix.sync.aligned.m8n8.x4.shared.b16 {%0,%1,%2,%3}, [%4];"
                 : "=r"(r0), "=r"(r1), "=r"(r2), "=r"(r3) : "r"(addr));
}

__device__ __forceinline__ void mma_f16(float* c, const uint32_t* a, uint32_t b0, uint32_t b1) {
    asm volatile(
        "mma.sync.aligned.m16n8k16.row.col.f32.f16.f16.f32 "
        "{%0,%1,%2,%3}, {%4,%5,%6,%7}, {%8,%9}, {%0,%1,%2,%3};"
        : "+f"(c[0]), "+f"(c[1]), "+f"(c[2]), "+f"(c[3])
        : "r"(a[0]), "r"(a[1]), "r"(a[2]), "r"(a[3]), "r"(b0), "r"(b1));
}

// ---------------- edge dtype probe + normalize -------------------------------
__global__ void reset_kernel(int Nn) {
    int i = blockIdx.x * blockDim.x + threadIdx.x;
    if (i < Nn) g_cnt[i] = 0;
    if (i == 0) g_is32 = 0;
}

__global__ void probe_kernel(const void* __restrict__ ei, int E, int Nn) {
    int e = blockIdx.x * blockDim.x + threadIdx.x;
    if (e >= E) return;
    long long v = ((const long long*)ei)[e];
    if (v < 0 || v >= (long long)Nn) g_is32 = 1;
}

__global__ void convert_hist_kernel(const void* __restrict__ ei, int E, int Nn) {
    int e = blockIdx.x * blockDim.x + threadIdx.x;
    if (e >= E) return;
    long long s, d;
    if (g_is32) {
        const int* p = (const int*)ei;
        s = p[e]; d = p[E + e];
    } else {
        const long long* p = (const long long*)ei;
        s = p[e]; d = p[E + e];
    }
    if (s < 0) s = 0; if (s >= Nn) s = Nn - 1;
    if (d < 0) d = 0; if (d >= Nn) d = Nn - 1;
    g_src[e] = (int)s;
    g_dst[e] = (int)d;
    atomicAdd(&g_cnt[(int)d], 1);
}

// ---------------- CSR scan + fill --------------------------------------------
__global__ void scan1_kernel(int Nn) {
    __shared__ int s[512];
    int i = blockIdx.x * 512 + threadIdx.x;
    int v = (i < Nn) ? g_cnt[i] : 0;
    s[threadIdx.x] = v;
    __syncthreads();
#pragma unroll
    for (int off = 1; off < 512; off <<= 1) {
        int t = (threadIdx.x >= off) ? s[threadIdx.x - off] : 0;
        __syncthreads();
        s[threadIdx.x] += t;
        __syncthreads();
    }
    if (i < Nn) g_rowptr[i] = s[threadIdx.x] - v;
    if (threadIdx.x == 511) g_bsums[blockIdx.x] = s[511];
}

__global__ void scan2_kernel(int nb) {
    __shared__ int s[256];
    int v = (threadIdx.x < nb) ? g_bsums[threadIdx.x] : 0;
    s[threadIdx.x] = v;
    __syncthreads();
#pragma unroll
    for (int off = 1; off < 256; off <<= 1) {
        int t = (threadIdx.x >= off) ? s[threadIdx.x - off] : 0;
        __syncthreads();
        s[threadIdx.x] += t;
        __syncthreads();
    }
    g_boffs[threadIdx.x] = s[threadIdx.x] - v;
}

__global__ void scan3_kernel(int Nn, int E) {
    int i = blockIdx.x * blockDim.x + threadIdx.x;
    if (i < Nn) {
        int r = g_rowptr[i] + g_boffs[i >> 9];
        g_rowptr[i] = r;
        g_cursor[i] = r;
    }
    if (i == 0) g_rowptr[Nn] = E;
}

__global__ void fill_kernel(int E) {
    int e = blockIdx.x * blockDim.x + threadIdx.x;
    if (e < E) {
        int pos = atomicAdd(&g_cursor[g_dst[e]], 1);
        g_esrc[pos] = g_src[e];
    }
}

// ---------------- fused conversions: W1, W2, x -> fp16 ------------------------
__global__ void conv_all_kernel(const float* __restrict__ W1l, const float* __restrict__ W1r,
                                const float* __restrict__ W2l, const float* __restrict__ W2r,
                                const float* __restrict__ x, int Nn) {
    int gid = blockIdx.x * blockDim.x + threadIdx.x;
    if (gid < 65536) {                       // W1 transposed
        int n = gid & 255, k = gid >> 8;
        float v = (k < 128) ? W1l[(size_t)k * 256 + n] : W1r[(size_t)(k - 128) * 256 + n];
        g_W1[n * 256 + k] = __float2half_rn(v);
    } else if (gid < 98304) {                // W2, n = [W2l|W2r]
        int g = gid - 65536;
        int n = g & 127, k = g >> 7;
        float v = (n < 64) ? W2l[(size_t)k * 64 + n] : W2r[(size_t)k * 64 + (n - 64)];
        g_W2[n * 256 + k] = __float2half_rn(v);
    } else {                                 // x -> fp16, cols 128..255 of A1
        int g = gid - 98304;
        if (g >= Nn * 32) return;
        int node = g >> 5;
        int c = (g & 31) * 4;
        float4 v = *(const float4*)(x + (size_t)node * 128 + c);
        __half2 p0 = __floats2half2_rn(v.x, v.y);
        __half2 p1 = __floats2half2_rn(v.z, v.w);
        *(uint2*)(g_a1 + (size_t)node * 256 + 128 + c) =
            make_uint2(*(uint32_t*)&p0, *(uint32_t*)&p1);
    }
}

// ---------------- gather-mean agg1: fp16 gather from g_a1 cols 128..255 -------
__global__ void agg1_kernel(int Nn) {
    int warp = (blockIdx.x * blockDim.x + threadIdx.x) >> 5;
    int lane = threadIdx.x & 31;
    if (warp >= Nn) return;
    int s0 = g_rowptr[warp], s1 = g_rowptr[warp + 1];
    float4 acc = make_float4(0.f, 0.f, 0.f, 0.f);
    for (int e = s0; e < s1; e++) {
        int src = g_esrc[e];
        uint2 u = *(const uint2*)(g_a1 + (size_t)src * 256 + 128 + lane * 4);
        float2 f0 = __half22float2(*(__half2*)&u.x);
        float2 f1 = __half22float2(*(__half2*)&u.y);
        acc.x += f0.x; acc.y += f0.y; acc.z += f1.x; acc.w += f1.y;
    }
    float inv = 1.f / fmaxf((float)(s1 - s0), 1.f);
    __half2 p0 = __floats2half2_rn(acc.x * inv, acc.y * inv);
    __half2 p1 = __floats2half2_rn(acc.z * inv, acc.w * inv);
    *(uint2*)(g_a1 + (size_t)warp * 256 + lane * 4) =
        make_uint2(*(uint32_t*)&p0, *(uint32_t*)&p1);
}

// ---------------- HMMA fp16 GEMM (single term) --------------------------------
#define ROWB 144
#define TILE_BYTES (128 * ROWB)

__device__ __forceinline__ void load_one(uint32_t sT, const __half* __restrict__ T,
                                         int row0, int k0, int tid) {
    int row = tid >> 1;
    const char* src = (const char*)(T + (size_t)(row0 + row) * 256 + k0) + (tid & 1) * 64;
    uint32_t d = sT + row * ROWB + (tid & 1) * 64;
#pragma unroll
    for (int j = 0; j < 4; j++) cp16(d + j * 16, src + j * 16);
}

// MODE 1: D[.,256] = [agg1|x] @ W1 ; +b1, relu -> g_h (fp16)
// MODE 2: D[.,128] = h @ [W2l|W2r] ; fp32 -> g_t (n<64) / g_o2 (n>=64)
template <int MODE>
__global__ __launch_bounds__(256, 2)
void mma_kernel(const float* __restrict__ bias, int Nn) {
    extern __shared__ char sm[];
    const uint32_t smb = smem_u32(sm);
    const uint32_t Abuf[2] = { smb, smb + TILE_BYTES };
    const uint32_t Bbuf[2] = { smb + 2 * TILE_BYTES, smb + 3 * TILE_BYTES };

    const int tid = threadIdx.x;
    const int wid = tid >> 5;
    const int lane = tid & 31;
    const int m0 = blockIdx.x * 128;
    const int n0 = blockIdx.y * 128;

    const __half* A = (MODE == 1) ? g_a1 : g_h;
    const __half* B = (MODE == 1) ? g_W1 : g_W2;

    const int wm = (wid >> 2) * 64;
    const int wn = (wid & 3) * 32;
    const int lrow = lane & 15;
    const int lcol8 = (lane >> 4) * 8;

    float acc[4][4][4];
#pragma unroll
    for (int i = 0; i < 4; i++)
#pragma unroll
        for (int j = 0; j < 4; j++)
#pragma unroll
            for (int q = 0; q < 4; q++) acc[i][j][q] = 0.f;

    // prologue: chunk 0
    load_one(Abuf[0], A, m0, 0, tid);
    load_one(Bbuf[0], B, n0, 0, tid);
    cp_commit();
    cp_wait0();
    __syncthreads();

    for (int s = 0; s < 4; s++) {
        int sn = s + 1;
        if (sn < 4) {
            load_one(Abuf[sn & 1], A, m0, sn * 64, tid);
            load_one(Bbuf[sn & 1], B, n0, sn * 64, tid);
            cp_commit();
        }
        uint32_t sA = Abuf[s & 1], sB = Bbuf[s & 1];
#pragma unroll
        for (int ks = 0; ks < 4; ks++) {
            int kb = ks * 16 + lcol8;
            uint32_t a[4][4], b[2][4];
#pragma unroll
            for (int mt = 0; mt < 4; mt++)
                ldsm_x4(a[mt][0], a[mt][1], a[mt][2], a[mt][3],
                        sA + (wm + mt * 16 + lrow) * ROWB + kb * 2);
#pragma unroll
            for (int p = 0; p < 2; p++)
                ldsm_x4(b[p][0], b[p][1], b[p][2], b[p][3],
                        sB + (wn + p * 16 + lrow) * ROWB + kb * 2);
#pragma unroll
            for (int mt = 0; mt < 4; mt++)
#pragma unroll
                for (int nt = 0; nt < 4; nt++)
                    mma_f16(acc[mt][nt], a[mt], b[nt >> 1][nt & 1], b[nt >> 1][(nt & 1) + 2]);
        }
        if (sn < 4) cp_wait0();
        __syncthreads();
    }

    // epilogue
#pragma unroll
    for (int mt = 0; mt < 4; mt++) {
        int r0 = m0 + wm + mt * 16 + (lane >> 2);
#pragma unroll
        for (int nt = 0; nt < 4; nt++) {
            int colL = wn + nt * 8 + (lane & 3) * 2;
            if (MODE == 1) {
                int col = n0 + colL;
                float bb0 = __ldg(bias + col), bb1 = __ldg(bias + col + 1);
#pragma unroll
                for (int h = 0; h < 2; h++) {
                    int r = r0 + h * 8;
                    if (r < Nn) {
                        float v0 = fmaxf(acc[mt][nt][2 * h + 0] + bb0, 0.f);
                        float v1 = fmaxf(acc[mt][nt][2 * h + 1] + bb1, 0.f);
                        __half2 p = __floats2half2_rn(v0, v1);
                        *(uint32_t*)(g_h + (size_t)r * 256 + col) = *(uint32_t*)&p;
                    }
                }
            } else {
#pragma unroll
                for (int h = 0; h < 2; h++) {
                    int r = r0 + h * 8;
                    if (r < Nn) {
                        float2 v = make_float2(acc[mt][nt][2 * h + 0], acc[mt][nt][2 * h + 1]);
                        if (colL < 64)
                            *(float2*)(g_t + (size_t)r * 64 + colL) = v;
                        else
                            *(float2*)(g_o2 + (size_t)r * 64 + (colL - 64)) = v;
                    }
                }
            }
        }
    }
}

// ---------------- agg2 + final fused: out = o2 + b2 + mean(gather t) ----------
__global__ void agg2_final_kernel(const float* __restrict__ b2,
                                  float* __restrict__ out, int Nn) {
    int warp = (blockIdx.x * blockDim.x + threadIdx.x) >> 5;
    int lane = threadIdx.x & 31;
    if (warp >= Nn) return;
    int s0 = g_rowptr[warp], s1 = g_rowptr[warp + 1];
    float2 acc = make_float2(0.f, 0.f);
    for (int e = s0; e < s1; e++) {
        int src = g_esrc[e];
        float2 v = *(const float2*)(g_t + (size_t)src * 64 + lane * 2);
        acc.x += v.x; acc.y += v.y;
    }
    float inv = 1.f / fmaxf((float)(s1 - s0), 1.f);
    float2 o = *(const float2*)(g_o2 + (size_t)warp * 64 + lane * 2);
    float2 bb = *(const float2*)(b2 + lane * 2);
    float2 v = make_float2(acc.x * inv + o.x + bb.x, acc.y * inv + o.y + bb.y);
    *(float2*)(out + (size_t)warp * 64 + lane * 2) = v;
}

// ---------------- launch -------------------------------------------------------
extern "C" void kernel_launch(void* const* d_in, const int* in_sizes, int n_in,
                              void* d_out, int out_size) {
    const float* x   = (const float*)d_in[0];
    const void*  ei  = d_in[1];
    const float* W1l = (const float*)d_in[2];
    const float* b1  = (const float*)d_in[3];
    const float* W1r = (const float*)d_in[4];
    const float* W2l = (const float*)d_in[5];
    const float* b2  = (const float*)d_in[6];
    const float* W2r = (const float*)d_in[7];
    float*       out = (float*)d_out;

    const int Nn = in_sizes[0] / 128;
    const int E  = in_sizes[1] / 2;
    const int nb = (Nn + 511) / 512;

    const int SMEM = 4 * TILE_BYTES;   // 73728
    cudaFuncSetAttribute(mma_kernel<1>, cudaFuncAttributeMaxDynamicSharedMemorySize, SMEM);
    cudaFuncSetAttribute(mma_kernel<2>, cudaFuncAttributeMaxDynamicSharedMemorySize, SMEM);

    reset_kernel<<<(Nn + 255) / 256, 256>>>(Nn);
    probe_kernel<<<(E + 255) / 256, 256>>>(ei, E, Nn);
    convert_hist_kernel<<<(E + 255) / 256, 256>>>(ei, E, Nn);
    scan1_kernel<<<nb, 512>>>(Nn);
    scan2_kernel<<<1, 256>>>(nb);
    scan3_kernel<<<(Nn + 255) / 256, 256>>>(Nn, E);
    fill_kernel<<<(E + 255) / 256, 256>>>(E);

    conv_all_kernel<<<(98304 + Nn * 32 + 255) / 256, 256>>>(W1l, W1r, W2l, W2r, x, Nn);
    agg1_kernel<<<(Nn * 32 + 255) / 256, 256>>>(Nn);

    const int grid = (Nn + 127) / 128;
    mma_kernel<1><<<dim3(grid, 2), 256, SMEM>>>(b1, Nn);
    mma_kernel<2><<<dim3(grid, 1), 256, SMEM>>>(b2, Nn);
    agg2_final_kernel<<<(Nn * 32 + 255) / 256, 256>>>(b2, out, Nn);
}

// round 9
// speedup vs baseline: 2.9467x; 1.0165x over previous
#include <cuda_runtime.h>
#include <cuda_fp16.h>
#include <cstdint>

#define N_MAX 100000
#define N_PAD 100096
#define E_MAX 400000

// ---------------- scratch ---------------------------------------------------
__device__ __align__(16) __half g_a1[(size_t)N_PAD * 256];   // [agg1|x] fp16
__device__ __align__(16) __half g_h [(size_t)N_PAD * 256];   // hidden fp16
__device__ __align__(16) __half g_t2[(size_t)N_MAX * 128];   // [t | o2] fp16
__device__ __align__(16) __half g_W1[256 * 256];             // [n][k]
__device__ __align__(16) __half g_W2[128 * 256];             // [n][k], n=[W2l|W2r]
__device__ int g_src[E_MAX], g_dst[E_MAX];
__device__ int g_cnt[N_MAX];          // zero-initialized; re-zeroed by scan3 each run
__device__ int g_rowptr[N_MAX + 1], g_cursor[N_MAX], g_esrc[E_MAX];
__device__ int g_bsums[256], g_boffs[256];
__device__ int g_is32;                // zero-initialized; re-zeroed by scan3 each run

// ---------------- helpers ---------------------------------------------------
__device__ __forceinline__ uint32_t smem_u32(const void* p) {
    uint32_t a;
    asm("{ .reg .u64 t; cvta.to.shared.u64 t, %1; cvt.u32.u64 %0, t; }" : "=r"(a) : "l"(p));
    return a;
}

__device__ __forceinline__ void cp16(uint32_t dst, const void* src) {
    asm volatile("cp.async.cg.shared.global [%0], [%1], 16;" :: "r"(dst), "l"(src) : "memory");
}
__device__ __forceinline__ void cp_commit() {
    asm volatile("cp.async.commit_group;" ::: "memory");
}
__device__ __forceinline__ void cp_wait0() {
    asm volatile("cp.async.wait_group 0;" ::: "memory");
}

__device__ __forceinline__ void ldsm_x4(uint32_t& r0, uint32_t& r1, uint32_t& r2, uint32_t& r3,
                                        uint32_t addr) {
    asm volatile("ldmatrix.sync.aligned.m8n8.x4.shared.b16 {%0,%1,%2,%3}, [%4];"
                 : "=r"(r0), "=r"(r1), "=r"(r2), "=r"(r3) : "r"(addr));
}

__device__ __forceinline__ void mma_f16(float* c, const uint32_t* a, uint32_t b0, uint32_t b1) {
    asm volatile(
        "mma.sync.aligned.m16n8k16.row.col.f32.f16.f16.f32 "
        "{%0,%1,%2,%3}, {%4,%5,%6,%7}, {%8,%9}, {%0,%1,%2,%3};"
        : "+f"(c[0]), "+f"(c[1]), "+f"(c[2]), "+f"(c[3])
        : "r"(a[0]), "r"(a[1]), "r"(a[2]), "r"(a[3]), "r"(b0), "r"(b1));
}

// ---------------- edge dtype probe -------------------------------------------
__global__ void probe_kernel(const void* __restrict__ ei, int E, int Nn) {
    int e = blockIdx.x * blockDim.x + threadIdx.x;
    if (e >= E) return;
    long long v = ((const long long*)ei)[e];
    if (v < 0 || v >= (long long)Nn) g_is32 = 1;
}

// convert + histogram fused (g_cnt must be zero at entry; scan3 restores it)
__global__ void convert_hist_kernel(const void* __restrict__ ei, int E, int Nn) {
    int e = blockIdx.x * blockDim.x + threadIdx.x;
    if (e >= E) return;
    long long s, d;
    if (g_is32) {
        const int* p = (const int*)ei;
        s = p[e]; d = p[E + e];
    } else {
        const long long* p = (const long long*)ei;
        s = p[e]; d = p[E + e];
    }
    if (s < 0) s = 0; if (s >= Nn) s = Nn - 1;
    if (d < 0) d = 0; if (d >= Nn) d = Nn - 1;
    g_src[e] = (int)s;
    g_dst[e] = (int)d;
    atomicAdd(&g_cnt[(int)d], 1);
}

// ---------------- CSR scan + fill ---------------------------------------------
__global__ void scan1_kernel(int Nn) {
    __shared__ int s[512];
    int i = blockIdx.x * 512 + threadIdx.x;
    int v = (i < Nn) ? g_cnt[i] : 0;
    s[threadIdx.x] = v;
    __syncthreads();
#pragma unroll
    for (int off = 1; off < 512; off <<= 1) {
        int t = (threadIdx.x >= off) ? s[threadIdx.x - off] : 0;
        __syncthreads();
        s[threadIdx.x] += t;
        __syncthreads();
    }
    if (i < Nn) g_rowptr[i] = s[threadIdx.x] - v;
    if (threadIdx.x == 511) g_bsums[blockIdx.x] = s[511];
}

__global__ void scan2_kernel(int nb) {
    __shared__ int s[256];
    int v = (threadIdx.x < nb) ? g_bsums[threadIdx.x] : 0;
    s[threadIdx.x] = v;
    __syncthreads();
#pragma unroll
    for (int off = 1; off < 256; off <<= 1) {
        int t = (threadIdx.x >= off) ? s[threadIdx.x - off] : 0;
        __syncthreads();
        s[threadIdx.x] += t;
        __syncthreads();
    }
    g_boffs[threadIdx.x] = s[threadIdx.x] - v;
}

// also re-zeroes g_cnt / g_is32 so the NEXT kernel_launch call starts clean
__global__ void scan3_kernel(int Nn, int E) {
    int i = blockIdx.x * blockDim.x + threadIdx.x;
    if (i < Nn) {
        int r = g_rowptr[i] + g_boffs[i >> 9];
        g_rowptr[i] = r;
        g_cursor[i] = r;
        g_cnt[i] = 0;
    }
    if (i == 0) {
        g_rowptr[Nn] = E;
        g_is32 = 0;
    }
}

__global__ void fill_kernel(int E) {
    int e = blockIdx.x * blockDim.x + threadIdx.x;
    if (e < E) {
        int pos = atomicAdd(&g_cursor[g_dst[e]], 1);
        g_esrc[pos] = g_src[e];
    }
}

// ---------------- fused conversions: W1, W2, x -> fp16 -------------------------
__global__ void conv_all_kernel(const float* __restrict__ W1l, const float* __restrict__ W1r,
                                const float* __restrict__ W2l, const float* __restrict__ W2r,
                                const float* __restrict__ x, int Nn) {
    int gid = blockIdx.x * blockDim.x + threadIdx.x;
    if (gid < 65536) {                       // W1 transposed
        int n = gid & 255, k = gid >> 8;
        float v = (k < 128) ? W1l[(size_t)k * 256 + n] : W1r[(size_t)(k - 128) * 256 + n];
        g_W1[n * 256 + k] = __float2half_rn(v);
    } else if (gid < 98304) {                // W2, n = [W2l|W2r]
        int g = gid - 65536;
        int n = g & 127, k = g >> 7;
        float v = (n < 64) ? W2l[(size_t)k * 64 + n] : W2r[(size_t)k * 64 + (n - 64)];
        g_W2[n * 256 + k] = __float2half_rn(v);
    } else {                                 // x -> fp16, cols 128..255 of A1
        int g = gid - 98304;
        if (g >= Nn * 32) return;
        int node = g >> 5;
        int c = (g & 31) * 4;
        float4 v = *(const float4*)(x + (size_t)node * 128 + c);
        __half2 p0 = __floats2half2_rn(v.x, v.y);
        __half2 p1 = __floats2half2_rn(v.z, v.w);
        *(uint2*)(g_a1 + (size_t)node * 256 + 128 + c) =
            make_uint2(*(uint32_t*)&p0, *(uint32_t*)&p1);
    }
}

// ---------------- gather-mean agg1 (fp16, MLP-2) --------------------------------
__global__ void agg1_kernel(int Nn) {
    int warp = (blockIdx.x * blockDim.x + threadIdx.x) >> 5;
    int lane = threadIdx.x & 31;
    if (warp >= Nn) return;
    int s0 = g_rowptr[warp], s1 = g_rowptr[warp + 1];
    float4 acc = make_float4(0.f, 0.f, 0.f, 0.f);
    int e = s0;
    for (; e + 1 < s1; e += 2) {
        int sa = g_esrc[e], sb = g_esrc[e + 1];
        uint2 ua = *(const uint2*)(g_a1 + (size_t)sa * 256 + 128 + lane * 4);
        uint2 ub = *(const uint2*)(g_a1 + (size_t)sb * 256 + 128 + lane * 4);
        float2 a0 = __half22float2(*(__half2*)&ua.x);
        float2 a1 = __half22float2(*(__half2*)&ua.y);
        float2 b0 = __half22float2(*(__half2*)&ub.x);
        float2 b1 = __half22float2(*(__half2*)&ub.y);
        acc.x += a0.x + b0.x; acc.y += a0.y + b0.y;
        acc.z += a1.x + b1.x; acc.w += a1.y + b1.y;
    }
    if (e < s1) {
        int sa = g_esrc[e];
        uint2 ua = *(const uint2*)(g_a1 + (size_t)sa * 256 + 128 + lane * 4);
        float2 a0 = __half22float2(*(__half2*)&ua.x);
        float2 a1 = __half22float2(*(__half2*)&ua.y);
        acc.x += a0.x; acc.y += a0.y; acc.z += a1.x; acc.w += a1.y;
    }
    float inv = 1.f / fmaxf((float)(s1 - s0), 1.f);
    __half2 p0 = __floats2half2_rn(acc.x * inv, acc.y * inv);
    __half2 p1 = __floats2half2_rn(acc.z * inv, acc.w * inv);
    *(uint2*)(g_a1 + (size_t)warp * 256 + lane * 4) =
        make_uint2(*(uint32_t*)&p0, *(uint32_t*)&p1);
}

// ---------------- HMMA fp16 GEMM --------------------------------------------------
#define ROWB 144
#define TILE_BYTES (128 * ROWB)

__device__ __forceinline__ void load_one(uint32_t sT, const __half* __restrict__ T,
                                         int row0, int k0, int tid) {
    int row = tid >> 1;
    const char* src = (const char*)(T + (size_t)(row0 + row) * 256 + k0) + (tid & 1) * 64;
    uint32_t d = sT + row * ROWB + (tid & 1) * 64;
#pragma unroll
    for (int j = 0; j < 4; j++) cp16(d + j * 16, src + j * 16);
}

// MODE 1: D[.,256] = [agg1|x] @ W1 ; +b1, relu -> g_h (fp16)
// MODE 2: D[.,128] = h @ [W2l|W2r] ; fp16 -> g_t2 (t cols 0-63, o2 cols 64-127)
template <int MODE>
__global__ __launch_bounds__(256, 2)
void mma_kernel(const float* __restrict__ bias, int Nn) {
    extern __shared__ char sm[];
    const uint32_t smb = smem_u32(sm);
    const uint32_t Abuf[2] = { smb, smb + TILE_BYTES };
    const uint32_t Bbuf[2] = { smb + 2 * TILE_BYTES, smb + 3 * TILE_BYTES };

    const int tid = threadIdx.x;
    const int wid = tid >> 5;
    const int lane = tid & 31;
    const int m0 = blockIdx.x * 128;
    const int n0 = blockIdx.y * 128;

    const __half* A = (MODE == 1) ? g_a1 : g_h;
    const __half* B = (MODE == 1) ? g_W1 : g_W2;

    const int wm = (wid >> 2) * 64;
    const int wn = (wid & 3) * 32;
    const int lrow = lane & 15;
    const int lcol8 = (lane >> 4) * 8;

    float acc[4][4][4];
#pragma unroll
    for (int i = 0; i < 4; i++)
#pragma unroll
        for (int j = 0; j < 4; j++)
#pragma unroll
            for (int q = 0; q < 4; q++) acc[i][j][q] = 0.f;

    load_one(Abuf[0], A, m0, 0, tid);
    load_one(Bbuf[0], B, n0, 0, tid);
    cp_commit();
    cp_wait0();
    __syncthreads();

    for (int s = 0; s < 4; s++) {
        int sn = s + 1;
        if (sn < 4) {
            load_one(Abuf[sn & 1], A, m0, sn * 64, tid);
            load_one(Bbuf[sn & 1], B, n0, sn * 64, tid);
            cp_commit();
        }
        uint32_t sA = Abuf[s & 1], sB = Bbuf[s & 1];
#pragma unroll
        for (int ks = 0; ks < 4; ks++) {
            int kb = ks * 16 + lcol8;
            uint32_t a[4][4], b[2][4];
#pragma unroll
            for (int mt = 0; mt < 4; mt++)
                ldsm_x4(a[mt][0], a[mt][1], a[mt][2], a[mt][3],
                        sA + (wm + mt * 16 + lrow) * ROWB + kb * 2);
#pragma unroll
            for (int p = 0; p < 2; p++)
                ldsm_x4(b[p][0], b[p][1], b[p][2], b[p][3],
                        sB + (wn + p * 16 + lrow) * ROWB + kb * 2);
#pragma unroll
            for (int mt = 0; mt < 4; mt++)
#pragma unroll
                for (int nt = 0; nt < 4; nt++)
                    mma_f16(acc[mt][nt], a[mt], b[nt >> 1][nt & 1], b[nt >> 1][(nt & 1) + 2]);
        }
        if (sn < 4) cp_wait0();
        __syncthreads();
    }

    // epilogue
#pragma unroll
    for (int mt = 0; mt < 4; mt++) {
        int r0 = m0 + wm + mt * 16 + (lane >> 2);
#pragma unroll
        for (int nt = 0; nt < 4; nt++) {
            int colL = wn + nt * 8 + (lane & 3) * 2;
            if (MODE == 1) {
                int col = n0 + colL;
                float bb0 = __ldg(bias + col), bb1 = __ldg(bias + col + 1);
#pragma unroll
                for (int h = 0; h < 2; h++) {
                    int r = r0 + h * 8;
                    if (r < Nn) {
                        float v0 = fmaxf(acc[mt][nt][2 * h + 0] + bb0, 0.f);
                        float v1 = fmaxf(acc[mt][nt][2 * h + 1] + bb1, 0.f);
                        __half2 p = __floats2half2_rn(v0, v1);
                        *(uint32_t*)(g_h + (size_t)r * 256 + col) = *(uint32_t*)&p;
                    }
                }
            } else {
#pragma unroll
                for (int h = 0; h < 2; h++) {
                    int r = r0 + h * 8;
                    if (r < Nn) {
                        __half2 p = __floats2half2_rn(acc[mt][nt][2 * h + 0],
                                                      acc[mt][nt][2 * h + 1]);
                        *(uint32_t*)(g_t2 + (size_t)r * 128 + colL) = *(uint32_t*)&p;
                    }
                }
            }
        }
    }
}

// ---------------- agg2 + final fused (fp16 gather, MLP-2) -----------------------
// out[node] = mean(gather t) + o2[node] + b2 ; t = g_t2 cols 0-63, o2 = cols 64-127
__global__ void agg2_final_kernel(const float* __restrict__ b2,
                                  float* __restrict__ out, int Nn) {
    int warp = (blockIdx.x * blockDim.x + threadIdx.x) >> 5;
    int lane = threadIdx.x & 31;
    if (warp >= Nn) return;
    int s0 = g_rowptr[warp], s1 = g_rowptr[warp + 1];
    float2 acc = make_float2(0.f, 0.f);
    int e = s0;
    for (; e + 1 < s1; e += 2) {
        int sa = g_esrc[e], sb = g_esrc[e + 1];
        uint32_t ua = *(const uint32_t*)(g_t2 + (size_t)sa * 128 + lane * 2);
        uint32_t ub = *(const uint32_t*)(g_t2 + (size_t)sb * 128 + lane * 2);
        float2 fa = __half22float2(*(__half2*)&ua);
        float2 fb = __half22float2(*(__half2*)&ub);
        acc.x += fa.x + fb.x; acc.y += fa.y + fb.y;
    }
    if (e < s1) {
        int sa = g_esrc[e];
        uint32_t ua = *(const uint32_t*)(g_t2 + (size_t)sa * 128 + lane * 2);
        float2 fa = __half22float2(*(__half2*)&ua);
        acc.x += fa.x; acc.y += fa.y;
    }
    float inv = 1.f / fmaxf((float)(s1 - s0), 1.f);
    uint32_t uo = *(const uint32_t*)(g_t2 + (size_t)warp * 128 + 64 + lane * 2);
    float2 o = __half22float2(*(__half2*)&uo);
    float2 bb = *(const float2*)(b2 + lane * 2);
    float2 v = make_float2(acc.x * inv + o.x + bb.x, acc.y * inv + o.y + bb.y);
    *(float2*)(out + (size_t)warp * 64 + lane * 2) = v;
}

// ---------------- launch ----------------------------------------------------------
extern "C" void kernel_launch(void* const* d_in, const int* in_sizes, int n_in,
                              void* d_out, int out_size) {
    const float* x   = (const float*)d_in[0];
    const void*  ei  = d_in[1];
    const float* W1l = (const float*)d_in[2];
    const float* b1  = (const float*)d_in[3];
    const float* W1r = (const float*)d_in[4];
    const float* W2l = (const float*)d_in[5];
    const float* b2  = (const float*)d_in[6];
    const float* W2r = (const float*)d_in[7];
    float*       out = (float*)d_out;

    const int Nn = in_sizes[0] / 128;
    const int E  = in_sizes[1] / 2;
    const int nb = (Nn + 511) / 512;

    const int SMEM = 4 * TILE_BYTES;   // 73728
    cudaFuncSetAttribute(mma_kernel<1>, cudaFuncAttributeMaxDynamicSharedMemorySize, SMEM);
    cudaFuncSetAttribute(mma_kernel<2>, cudaFuncAttributeMaxDynamicSharedMemorySize, SMEM);

    probe_kernel<<<(E + 255) / 256, 256>>>(ei, E, Nn);
    convert_hist_kernel<<<(E + 255) / 256, 256>>>(ei, E, Nn);
    scan1_kernel<<<nb, 512>>>(Nn);
    scan2_kernel<<<1, 256>>>(nb);
    scan3_kernel<<<(Nn + 255) / 256, 256>>>(Nn, E);   // also re-zeroes g_cnt/g_is32
    fill_kernel<<<(E + 255) / 256, 256>>>(E);

    conv_all_kernel<<<(98304 + Nn * 32 + 255) / 256, 256>>>(W1l, W1r, W2l, W2r, x, Nn);
    agg1_kernel<<<(Nn * 32 + 255) / 256, 256>>>(Nn);

    const int grid = (Nn + 127) / 128;
    mma_kernel<1><<<dim3(grid, 2), 256, SMEM>>>(b1, Nn);
    mma_kernel<2><<<dim3(grid, 1), 256, SMEM>>>(b2, Nn);
    agg2_final_kernel<<<(Nn * 32 + 255) / 256, 256>>>(b2, out, Nn);
}